// round 14
// baseline (speedup 1.0000x reference)
#include <cuda_runtime.h>
#include <cuda_fp16.h>
#include <math.h>
#include <stdint.h>

#define Bq 2
#define SEQ 2048
#define Dm 1024
#define NCx 77
#define DCx 768
#define Hh 16
#define DHd 64
#define FFd 4096
#define SCALE_ATTN 0.125f
#define EPS_LN 1e-5f
#define MROWS (Bq*SEQ)          // 4096
#define CROWS (Bq*NCx)          // 154

// ---------------- scratch ----------------
__device__ __half g_hh[(size_t)MROWS*Dm];
__device__ __half g_qkv[(size_t)MROWS*3*Dm];
__device__ __half g_kh[(size_t)CROWS*Dm + 1024];
__device__ __half g_vh[(size_t)CROWS*Dm + 1024];
__device__ __half g_atth[(size_t)MROWS*Dm];
__device__ __half g_th[(size_t)MROWS*FFd];
__device__ __half g_wh[(size_t)18874368];        // transposed half weights [N,K]

#define OWQKV 0
#define OW1O 3145728
#define OW2Q 4194304
#define OW2O 5242880
#define OFW1 6291456
#define OFW2 14680064

// ---------------- helpers ----------------
__device__ __forceinline__ float ex2f(float x) {
    float y;
    asm("ex2.approx.f32 %0, %1;" : "=f"(y) : "f"(x));
    return y;
}
// pack two floats to a half2 fragment (lo in lower 16 bits) — matches __floats2half2_rn(lo,hi)
__device__ __forceinline__ uint32_t pack_h2(float lo, float hi) {
    uint32_t u;
    asm("cvt.rn.f16x2.f32 %0, %1, %2;" : "=r"(u) : "f"(hi), "f"(lo));
    return u;
}
__device__ __forceinline__ void mma_f16(float c[4],
                                        uint32_t a0, uint32_t a1, uint32_t a2, uint32_t a3,
                                        uint32_t b0, uint32_t b1) {
    asm volatile(
        "mma.sync.aligned.m16n8k16.row.col.f32.f16.f16.f32 "
        "{%0,%1,%2,%3}, {%4,%5,%6,%7}, {%8,%9}, {%0,%1,%2,%3};"
        : "+f"(c[0]), "+f"(c[1]), "+f"(c[2]), "+f"(c[3])
        : "r"(a0), "r"(a1), "r"(a2), "r"(a3), "r"(b0), "r"(b1));
}
__device__ __forceinline__ void ldsm4(uint32_t& r0, uint32_t& r1, uint32_t& r2, uint32_t& r3,
                                      uint32_t addr) {
    asm volatile("ldmatrix.sync.aligned.m8n8.x4.shared.b16 {%0,%1,%2,%3}, [%4];"
                 : "=r"(r0), "=r"(r1), "=r"(r2), "=r"(r3) : "r"(addr));
}
__device__ __forceinline__ void ldsm4t(uint32_t& r0, uint32_t& r1, uint32_t& r2, uint32_t& r3,
                                       uint32_t addr) {
    asm volatile("ldmatrix.sync.aligned.m8n8.x4.trans.shared.b16 {%0,%1,%2,%3}, [%4];"
                 : "=r"(r0), "=r"(r1), "=r"(r2), "=r"(r3) : "r"(addr));
}
__device__ __forceinline__ void cpa16(uint32_t dst, const void* src) {
    asm volatile("cp.async.cg.shared.global [%0], [%1], 16;" :: "r"(dst), "l"(src));
}
#define CP_COMMIT() asm volatile("cp.async.commit_group;")
#define CP_WAIT1()  asm volatile("cp.async.wait_group 1;")
#define CP_WAIT0()  asm volatile("cp.async.wait_group 0;")

// ---------------- weight transpose + fp16 convert ----------------
__global__ void transpose_half6(const float* s0, const float* s1, const float* s2,
                                const float* s3, const float* s4, const float* s5,
                                __half* d0, __half* d1, __half* d2,
                                __half* d3, __half* d4, __half* d5) {
    const float* src; __half* dst;
    switch (blockIdx.z) {
        case 0: src = s0; dst = d0; break;
        case 1: src = s1; dst = d1; break;
        case 2: src = s2; dst = d2; break;
        case 3: src = s3; dst = d3; break;
        case 4: src = s4; dst = d4; break;
        default: src = s5; dst = d5; break;
    }
    __shared__ float t[32][33];
    int bx = blockIdx.x * 32;
    int by = blockIdx.y * 32;
    int x = bx + threadIdx.x;
    #pragma unroll
    for (int i = 0; i < 32; i += 8) {
        int y = by + threadIdx.y + i;
        t[threadIdx.y + i][threadIdx.x] = src[(size_t)y * Dm + x];
    }
    __syncthreads();
    int kx = by + threadIdx.x;
    #pragma unroll
    for (int i = 0; i < 32; i += 8) {
        int ny = bx + threadIdx.y + i;
        dst[(size_t)ny * Dm + kx] = __float2half(t[threadIdx.x][threadIdx.y + i]);
    }
}
__global__ void transpose_half(const float* __restrict__ src, __half* __restrict__ dst,
                               int K, int N) {
    __shared__ float t[32][33];
    int bx = blockIdx.x * 32;
    int by = blockIdx.y * 32;
    int x = bx + threadIdx.x;
    #pragma unroll
    for (int i = 0; i < 32; i += 8) {
        int y = by + threadIdx.y + i;
        t[threadIdx.y + i][threadIdx.x] = src[(size_t)y * N + x];
    }
    __syncthreads();
    int kx = by + threadIdx.x;
    #pragma unroll
    for (int i = 0; i < 32; i += 8) {
        int ny = bx + threadIdx.y + i;
        dst[(size_t)ny * K + kx] = __float2half(t[threadIdx.x][threadIdx.y + i]);
    }
}
__global__ void transpose_geglu(const float* __restrict__ src, __half* __restrict__ dst,
                                int K, int N) {
    __shared__ float t[32][33];
    int bx = blockIdx.x * 32;
    int by = blockIdx.y * 32;
    int x = bx + threadIdx.x;
    #pragma unroll
    for (int i = 0; i < 32; i += 8) {
        int y = by + threadIdx.y + i;
        t[threadIdx.y + i][threadIdx.x] = src[(size_t)y * N + x];
    }
    __syncthreads();
    int kx = by + threadIdx.x;
    #pragma unroll
    for (int i = 0; i < 32; i += 8) {
        int ny = bx + threadIdx.y + i;
        int iny = (ny < FFd) ? (2*ny) : (2*(ny - FFd) + 1);
        dst[(size_t)iny * K + kx] = __float2half(t[threadIdx.x][threadIdx.y + i]);
    }
}

// ================= fp16 dense GEMM (ldmatrix, BK=64, 2-stage, 3 CTA/SM) =====
#define ASH 72
#define HTILE (128*ASH)
#define GH_SMEM (2*2*HTILE*2)

template<int MODE>
__global__ __launch_bounds__(256, 3)
void gemm_h(const __half* __restrict__ A, const __half* __restrict__ Bt,
            const float* __restrict__ bias, const float* __restrict__ res,
            void* __restrict__ Cv, int M, int N, int K) {
    extern __shared__ __half smh[];
    __half* As = smh;
    __half* Bs = smh + 2*HTILE;
    int bm = blockIdx.y * 128, bn = blockIdx.x * 128;
    int tid = threadIdx.x, warp = tid >> 5, lane = tid & 31;
    int grp = lane >> 2, tig = lane & 3;
    int wm = (warp >> 2) * 64, wn = (warp & 3) * 32;
    int sel = lane >> 3, lrow = lane & 7;
    int a_r = (sel & 1) * 8 + lrow, a_c = (sel >> 1) * 8;
    int b_r = (sel >> 1) * 8 + lrow, b_c = (sel & 1) * 8;
    uint32_t sAu = (uint32_t)__cvta_generic_to_shared(As);
    uint32_t sBu = (uint32_t)__cvta_generic_to_shared(Bs);
    int niter = K >> 6;

    float acc[4][4][4] = {};

    auto loadTile = [&](int it, int buf) {
        int k0 = it * 64;
        #pragma unroll
        for (int i = 0; i < 4; i++) {
            int c = tid + i * 256;
            int row = c >> 3, kq = c & 7;
            cpa16(sAu + (uint32_t)(buf*HTILE + row*ASH + kq*8) * 2,
                  A + (size_t)(bm + row) * K + k0 + kq * 8);
            cpa16(sBu + (uint32_t)(buf*HTILE + row*ASH + kq*8) * 2,
                  Bt + (size_t)(bn + row) * K + k0 + kq * 8);
        }
        CP_COMMIT();
    };

    loadTile(0, 0);

    for (int it = 0; it < niter; ++it) {
        int buf = it & 1;
        CP_WAIT0();
        __syncthreads();
        if (it + 1 < niter) loadTile(it + 1, buf ^ 1);

        uint32_t Abu = sAu + (uint32_t)(buf * HTILE) * 2;
        uint32_t Bbu = sBu + (uint32_t)(buf * HTILE) * 2;
        #pragma unroll
        for (int ks = 0; ks < 64; ks += 16) {
            uint32_t af[4][4], bf[4][2];
            #pragma unroll
            for (int mf = 0; mf < 4; mf++) {
                uint32_t ad = Abu + (uint32_t)((wm + mf*16 + a_r) * ASH + ks + a_c) * 2;
                ldsm4(af[mf][0], af[mf][1], af[mf][2], af[mf][3], ad);
            }
            #pragma unroll
            for (int np = 0; np < 2; np++) {
                uint32_t bd = Bbu + (uint32_t)((wn + np*16 + b_r) * ASH + ks + b_c) * 2;
                ldsm4(bf[2*np][0], bf[2*np][1], bf[2*np+1][0], bf[2*np+1][1], bd);
            }
            #pragma unroll
            for (int mf = 0; mf < 4; mf++)
                #pragma unroll
                for (int nf = 0; nf < 4; nf++)
                    mma_f16(acc[mf][nf], af[mf][0], af[mf][1], af[mf][2], af[mf][3],
                            bf[nf][0], bf[nf][1]);
        }
    }

    #pragma unroll
    for (int mf = 0; mf < 4; mf++) {
        #pragma unroll
        for (int nf = 0; nf < 4; nf++) {
            int r = bm + wm + mf*16 + grp;
            int c = bn + wn + nf*8 + tig*2;
            float2 v0 = make_float2(acc[mf][nf][0], acc[mf][nf][1]);
            float2 v1 = make_float2(acc[mf][nf][2], acc[mf][nf][3]);
            if (MODE == 2) {
                int j = c >> 1;
                float bv = bias[j], bg = bias[FFd + j];
                float val0 = v0.x + bv, gat0 = v0.y + bg;
                float val1 = v1.x + bv, gat1 = v1.y + bg;
                float o0 = val0 * (0.5f * gat0 * (1.f + erff(gat0 * 0.70710678118654752f)));
                float o1 = val1 * (0.5f * gat1 * (1.f + erff(gat1 * 0.70710678118654752f)));
                __half* C = (__half*)Cv;
                C[(size_t)r * FFd + j]     = __float2half(o0);
                C[(size_t)(r+8) * FFd + j] = __float2half(o1);
            } else {
                if (bias) {
                    float2 bb = *(const float2*)(bias + c);
                    v0.x += bb.x; v0.y += bb.y; v1.x += bb.x; v1.y += bb.y;
                }
                if (MODE == 0 && res) {
                    float2 r0 = *(const float2*)(res + (size_t)r * N + c);
                    float2 r1 = *(const float2*)(res + (size_t)(r+8) * N + c);
                    v0.x += r0.x; v0.y += r0.y; v1.x += r1.x; v1.y += r1.y;
                }
                if (MODE == 1) {
                    __half* C = (__half*)Cv;
                    *(__half2*)(C + (size_t)r * N + c)     = __floats2half2_rn(v0.x, v0.y);
                    *(__half2*)(C + (size_t)(r+8) * N + c) = __floats2half2_rn(v1.x, v1.y);
                } else {
                    float* C = (float*)Cv;
                    *(float2*)(C + (size_t)r * N + c)     = v0;
                    *(float2*)(C + (size_t)(r+8) * N + c) = v1;
                }
            }
        }
    }
}

// ================= fp16 flash attention (register-P + double-buffered KV) ===
#define QSH 72
#define FTILE (128*QSH)
#define FLH_SMEM (5*FTILE*2)     // Q + 2*K + 2*V

__global__ __launch_bounds__(256, 2)
void flash_h(const __half* __restrict__ qkv, __half* __restrict__ o) {
    extern __shared__ __half smf[];
    __half* Qs = smf;
    uint32_t Qsu = (uint32_t)__cvta_generic_to_shared(Qs);
    uint32_t Ku[2] = { Qsu + (uint32_t)FTILE*2,   Qsu + (uint32_t)(2*FTILE)*2 };
    uint32_t Vu[2] = { Qsu + (uint32_t)(3*FTILE)*2, Qsu + (uint32_t)(4*FTILE)*2 };

    const int ldq = 3*Dm;
    int qt = blockIdx.x, bh = blockIdx.y;
    int b = bh >> 4, h = bh & 15;
    int tid = threadIdx.x, warp = tid >> 5, lane = tid & 31;
    int grp = lane >> 2, tig = lane & 3;
    int sel = lane >> 3, lrow = lane & 7;
    int a_r = (sel & 1) * 8 + lrow, a_c = (sel >> 1) * 8;
    int b_r = (sel >> 1) * 8 + lrow, b_c = (sel & 1) * 8;

    const __half* qb = qkv + ((size_t)b*SEQ + qt*128) * ldq + h*DHd;
    const __half* kb = qkv + (size_t)b*SEQ*ldq + Dm + h*DHd;
    const __half* vb = qkv + (size_t)b*SEQ*ldq + 2*Dm + h*DHd;

    {
        int row = tid >> 1, part = tid & 1;
        const float4* s4 = (const float4*)(qb + (size_t)row * ldq + part*32);
        float4* d4 = (float4*)(Qs + row*QSH + part*32);
        #pragma unroll
        for (int i = 0; i < 4; i++) d4[i] = s4[i];
    }

    auto loadKV = [&](int kv0, int buf) {
        #pragma unroll
        for (int i = 0; i < 4; i++) {
            int c = tid + i * 256;
            int row = c >> 3, kq = c & 7;
            cpa16(Ku[buf] + (uint32_t)(row*QSH + kq*8) * 2,
                  kb + (size_t)(kv0 + row) * ldq + kq * 8);
            cpa16(Vu[buf] + (uint32_t)(row*QSH + kq*8) * 2,
                  vb + (size_t)(kv0 + row) * ldq + kq * 8);
        }
        CP_COMMIT();
    };
    loadKV(0, 0);

    __syncthreads();
    uint32_t qf[4][4];
    {
        const __half* p = Qs + (warp*16 + grp) * QSH;
        #pragma unroll
        for (int ksi = 0; ksi < 4; ksi++) {
            qf[ksi][0] = *(const uint32_t*)(p + ksi*16 + tig*2);
            qf[ksi][1] = *(const uint32_t*)(p + 8*QSH + ksi*16 + tig*2);
            qf[ksi][2] = *(const uint32_t*)(p + ksi*16 + tig*2 + 8);
            qf[ksi][3] = *(const uint32_t*)(p + 8*QSH + ksi*16 + tig*2 + 8);
        }
    }

    float oacc[8][4] = {};
    float m0 = -1e30f, m1 = -1e30f, l0 = 0.f, l1 = 0.f;
    const float Csc = SCALE_ATTN * 1.4426950408889634f;

    for (int it = 0; it < SEQ/128; ++it) {
        int buf = it & 1;
        CP_WAIT0();
        __syncthreads();
        if (it + 1 < SEQ/128) loadKV((it + 1) * 128, buf ^ 1);

        float sacc[16][4] = {};
        #pragma unroll
        for (int ksi = 0; ksi < 4; ksi++) {
            #pragma unroll
            for (int np = 0; np < 8; np++) {
                uint32_t kd = Ku[buf] + (uint32_t)((np*16 + b_r) * QSH + ksi*16 + b_c) * 2;
                uint32_t b00, b01, b10, b11;
                ldsm4(b00, b01, b10, b11, kd);
                mma_f16(sacc[2*np],   qf[ksi][0], qf[ksi][1], qf[ksi][2], qf[ksi][3], b00, b01);
                mma_f16(sacc[2*np+1], qf[ksi][0], qf[ksi][1], qf[ksi][2], qf[ksi][3], b10, b11);
            }
        }
        float mx0 = -1e30f, mx1 = -1e30f;
        #pragma unroll
        for (int nf = 0; nf < 16; nf++) {
            sacc[nf][0] *= Csc; sacc[nf][1] *= Csc; sacc[nf][2] *= Csc; sacc[nf][3] *= Csc;
            mx0 = fmaxf(mx0, fmaxf(sacc[nf][0], sacc[nf][1]));
            mx1 = fmaxf(mx1, fmaxf(sacc[nf][2], sacc[nf][3]));
        }
        mx0 = fmaxf(mx0, __shfl_xor_sync(0xffffffffu, mx0, 1));
        mx0 = fmaxf(mx0, __shfl_xor_sync(0xffffffffu, mx0, 2));
        mx1 = fmaxf(mx1, __shfl_xor_sync(0xffffffffu, mx1, 1));
        mx1 = fmaxf(mx1, __shfl_xor_sync(0xffffffffu, mx1, 2));
        float mn0 = fmaxf(m0, mx0), mn1 = fmaxf(m1, mx1);
        float sc0 = ex2f(m0 - mn0), sc1 = ex2f(m1 - mn1);
        float sum0 = 0.f, sum1 = 0.f;
        uint32_t ph[16][2];
        #pragma unroll
        for (int nf = 0; nf < 16; nf++) {
            float p0 = ex2f(sacc[nf][0] - mn0);
            float p1 = ex2f(sacc[nf][1] - mn0);
            float p2 = ex2f(sacc[nf][2] - mn1);
            float p3 = ex2f(sacc[nf][3] - mn1);
            sum0 += p0 + p1; sum1 += p2 + p3;
            ph[nf][0] = pack_h2(p0, p1);
            ph[nf][1] = pack_h2(p2, p3);
        }
        sum0 += __shfl_xor_sync(0xffffffffu, sum0, 1);
        sum0 += __shfl_xor_sync(0xffffffffu, sum0, 2);
        sum1 += __shfl_xor_sync(0xffffffffu, sum1, 1);
        sum1 += __shfl_xor_sync(0xffffffffu, sum1, 2);
        l0 = l0 * sc0 + sum0;  l1 = l1 * sc1 + sum1;
        m0 = mn0;  m1 = mn1;
        #pragma unroll
        for (int nf = 0; nf < 8; nf++) {
            oacc[nf][0] *= sc0; oacc[nf][1] *= sc0;
            oacc[nf][2] *= sc1; oacc[nf][3] *= sc1;
        }

        #pragma unroll
        for (int ks = 0; ks < 8; ks++) {
            uint32_t a0 = ph[2*ks][0], a1 = ph[2*ks][1];
            uint32_t a2 = ph[2*ks+1][0], a3 = ph[2*ks+1][1];
            #pragma unroll
            for (int np = 0; np < 4; np++) {
                uint32_t vd = Vu[buf] + (uint32_t)((ks*16 + a_r) * QSH + np*16 + a_c) * 2;
                uint32_t b00, b01, b10, b11;
                ldsm4t(b00, b01, b10, b11, vd);
                mma_f16(oacc[2*np],   a0, a1, a2, a3, b00, b01);
                mma_f16(oacc[2*np+1], a0, a1, a2, a3, b10, b11);
            }
        }
    }

    float i0 = 1.f / l0, i1 = 1.f / l1;
    __half* ob = o + ((size_t)b*SEQ + qt*128 + warp*16) * Dm + h*DHd;
    #pragma unroll
    for (int nf = 0; nf < 8; nf++) {
        int c = nf*8 + tig*2;
        *(__half2*)(ob + (size_t)grp * Dm + c) =
            __floats2half2_rn(oacc[nf][0]*i0, oacc[nf][1]*i0);
        *(__half2*)(ob + (size_t)(grp+8) * Dm + c) =
            __floats2half2_rn(oacc[nf][2]*i1, oacc[nf][3]*i1);
    }
}

// ================= fp16 cross-attention (single KV tile, nk=77) =============
#define CKROWS 80
#define FLC_SMEM ((128*QSH + 2*CKROWS*QSH)*2)

__global__ __launch_bounds__(256, 2)
void flash_cross(const __half* __restrict__ q, const __half* __restrict__ k,
                 const __half* __restrict__ v, __half* __restrict__ o) {
    extern __shared__ __half smc[];
    __half* Qs = smc;
    __half* Ks = Qs + 128*QSH;
    __half* Vs = Ks + CKROWS*QSH;
    uint32_t Vsu = (uint32_t)__cvta_generic_to_shared(Vs);

    int qt = blockIdx.x, bh = blockIdx.y;
    int b = bh >> 4, h = bh & 15;
    int tid = threadIdx.x, warp = tid >> 5, lane = tid & 31;
    int grp = lane >> 2, tig = lane & 3;
    int sel = lane >> 3, lrow = lane & 7;
    int a_r = (sel & 1) * 8 + lrow, a_c = (sel >> 1) * 8;

    const __half* qb = q + ((size_t)b*SEQ + qt*128) * Dm + h*DHd;
    const __half* kb = k + (size_t)b*NCx*Dm + h*DHd;
    const __half* vb = v + (size_t)b*NCx*Dm + h*DHd;

    {
        int row = tid >> 1, part = tid & 1;
        const float4* s4 = (const float4*)(qb + (size_t)row * Dm + part*32);
        float4* d4 = (float4*)(Qs + row*QSH + part*32);
        #pragma unroll
        for (int i = 0; i < 4; i++) d4[i] = s4[i];
    }
    for (int rr = tid; rr < CKROWS*2; rr += 256) {
        int row = rr >> 1, part = rr & 1;
        float4* dk = (float4*)(Ks + row*QSH + part*32);
        float4* dv = (float4*)(Vs + row*QSH + part*32);
        if (row < NCx) {
            const float4* sk = (const float4*)(kb + (size_t)row * Dm + part*32);
            const float4* sv = (const float4*)(vb + (size_t)row * Dm + part*32);
            #pragma unroll
            for (int i = 0; i < 4; i++) { dk[i] = sk[i]; dv[i] = sv[i]; }
        } else {
            float4 z = make_float4(0.f,0.f,0.f,0.f);
            #pragma unroll
            for (int i = 0; i < 4; i++) { dk[i] = z; dv[i] = z; }
        }
    }
    __syncthreads();

    uint32_t qf[4][4];
    {
        const __half* p = Qs + (warp*16 + grp) * QSH;
        #pragma unroll
        for (int ksi = 0; ksi < 4; ksi++) {
            qf[ksi][0] = *(const uint32_t*)(p + ksi*16 + tig*2);
            qf[ksi][1] = *(const uint32_t*)(p + 8*QSH + ksi*16 + tig*2);
            qf[ksi][2] = *(const uint32_t*)(p + ksi*16 + tig*2 + 8);
            qf[ksi][3] = *(const uint32_t*)(p + 8*QSH + ksi*16 + tig*2 + 8);
        }
    }

    const float Csc = SCALE_ATTN * 1.4426950408889634f;

    float sacc[10][4] = {};
    #pragma unroll
    for (int ksi = 0; ksi < 4; ksi++) {
        #pragma unroll
        for (int nf = 0; nf < 10; nf++) {
            const __half* kp = Ks + (nf*8 + grp) * QSH + ksi*16;
            uint32_t b0 = *(const uint32_t*)(kp + tig*2);
            uint32_t b1 = *(const uint32_t*)(kp + tig*2 + 8);
            mma_f16(sacc[nf], qf[ksi][0], qf[ksi][1], qf[ksi][2], qf[ksi][3], b0, b1);
        }
    }
    float mx0 = -1e30f, mx1 = -1e30f;
    #pragma unroll
    for (int nf = 0; nf < 10; nf++) {
        int c0 = nf*8 + tig*2, c1 = c0 + 1;
        sacc[nf][0] = (c0 < NCx) ? sacc[nf][0]*Csc : -1e30f;
        sacc[nf][1] = (c1 < NCx) ? sacc[nf][1]*Csc : -1e30f;
        sacc[nf][2] = (c0 < NCx) ? sacc[nf][2]*Csc : -1e30f;
        sacc[nf][3] = (c1 < NCx) ? sacc[nf][3]*Csc : -1e30f;
        mx0 = fmaxf(mx0, fmaxf(sacc[nf][0], sacc[nf][1]));
        mx1 = fmaxf(mx1, fmaxf(sacc[nf][2], sacc[nf][3]));
    }
    mx0 = fmaxf(mx0, __shfl_xor_sync(0xffffffffu, mx0, 1));
    mx0 = fmaxf(mx0, __shfl_xor_sync(0xffffffffu, mx0, 2));
    mx1 = fmaxf(mx1, __shfl_xor_sync(0xffffffffu, mx1, 1));
    mx1 = fmaxf(mx1, __shfl_xor_sync(0xffffffffu, mx1, 2));

    float sum0 = 0.f, sum1 = 0.f;
    uint32_t ph[10][2];
    #pragma unroll
    for (int nf = 0; nf < 10; nf++) {
        float p0 = ex2f(sacc[nf][0] - mx0);
        float p1 = ex2f(sacc[nf][1] - mx0);
        float p2 = ex2f(sacc[nf][2] - mx1);
        float p3 = ex2f(sacc[nf][3] - mx1);
        sum0 += p0 + p1; sum1 += p2 + p3;
        ph[nf][0] = pack_h2(p0, p1);
        ph[nf][1] = pack_h2(p2, p3);
    }
    sum0 += __shfl_xor_sync(0xffffffffu, sum0, 1);
    sum0 += __shfl_xor_sync(0xffffffffu, sum0, 2);
    sum1 += __shfl_xor_sync(0xffffffffu, sum1, 1);
    sum1 += __shfl_xor_sync(0xffffffffu, sum1, 2);

    float oacc[8][4] = {};
    #pragma unroll
    for (int ks = 0; ks < 5; ks++) {
        uint32_t a0 = ph[2*ks][0], a1 = ph[2*ks][1];
        uint32_t a2 = ph[2*ks+1][0], a3 = ph[2*ks+1][1];
        #pragma unroll
        for (int np = 0; np < 4; np++) {
            uint32_t vd = Vsu + (uint32_t)((ks*16 + a_r) * QSH + np*16 + a_c) * 2;
            uint32_t b00, b01, b10, b11;
            ldsm4t(b00, b01, b10, b11, vd);
            mma_f16(oacc[2*np],   a0, a1, a2, a3, b00, b01);
            mma_f16(oacc[2*np+1], a0, a1, a2, a3, b10, b11);
        }
    }

    float i0 = 1.f / sum0, i1 = 1.f / sum1;
    __half* ob = o + ((size_t)b*SEQ + qt*128 + warp*16) * Dm + h*DHd;
    #pragma unroll
    for (int nf = 0; nf < 8; nf++) {
        int c = nf*8 + tig*2;
        *(__half2*)(ob + (size_t)grp * Dm + c) =
            __floats2half2_rn(oacc[nf][0]*i0, oacc[nf][1]*i0);
        *(__half2*)(ob + (size_t)(grp+8) * Dm + c) =
            __floats2half2_rn(oacc[nf][2]*i1, oacc[nf][3]*i1);
    }
}

// ---------------- layernorm: single-pass float4 + warp shuffle ----------------
__global__ __launch_bounds__(256)
void ln_kernel(const float* __restrict__ x, const float* __restrict__ g,
               const float* __restrict__ b, __half* __restrict__ out) {
    int row = blockIdx.x;
    int tid = threadIdx.x, warp = tid >> 5, lane = tid & 31;
    const float4* xr = (const float4*)(x + (size_t)row * Dm);
    float4 v = xr[tid];
    float s  = v.x + v.y + v.z + v.w;
    float ss = v.x*v.x + v.y*v.y + v.z*v.z + v.w*v.w;
    #pragma unroll
    for (int o = 16; o > 0; o >>= 1) {
        s  += __shfl_xor_sync(0xffffffffu, s,  o);
        ss += __shfl_xor_sync(0xffffffffu, ss, o);
    }
    __shared__ float ws[8], wss[8];
    if (lane == 0) { ws[warp] = s; wss[warp] = ss; }
    __syncthreads();
    float ts = 0.f, tss = 0.f;
    #pragma unroll
    for (int i = 0; i < 8; i++) { ts += ws[i]; tss += wss[i]; }
    float mu  = ts * (1.0f / Dm);
    float var = tss * (1.0f / Dm) - mu * mu;
    float inv = rsqrtf(var + EPS_LN);
    float4 gv = ((const float4*)g)[tid];
    float4 bv = ((const float4*)b)[tid];
    float o0 = (v.x - mu) * inv * gv.x + bv.x;
    float o1 = (v.y - mu) * inv * gv.y + bv.y;
    float o2 = (v.z - mu) * inv * gv.z + bv.z;
    float o3 = (v.w - mu) * inv * gv.w + bv.w;
    __half2* orow = (__half2*)(out + (size_t)row * Dm) + tid * 2;
    orow[0] = __floats2half2_rn(o0, o1);
    orow[1] = __floats2half2_rn(o2, o3);
}

__global__ void gemm_kv_h(const float* __restrict__ A,
                          const float* __restrict__ Wk, const float* __restrict__ Wv,
                          __half* __restrict__ Ck, __half* __restrict__ Cv,
                          int M, int K, int Nn) {
    __shared__ float As[64][17];
    __shared__ float Bs[16][64];
    const float* Bm = (blockIdx.z == 0) ? Wk : Wv;
    __half* C = (blockIdx.z == 0) ? Ck : Cv;
    int bm = blockIdx.y * 64, bn = blockIdx.x * 64;
    int tx = threadIdx.x & 15, ty = threadIdx.x >> 4;
    float acc[4][4] = {};
    for (int k0 = 0; k0 < K; k0 += 16) {
        #pragma unroll
        for (int i = 0; i < 4; i++) {
            int idx = threadIdx.x + i * 256;
            int r = idx >> 4, kk = idx & 15;
            int gr = bm + r;
            As[r][kk] = (gr < M) ? A[(size_t)gr * K + k0 + kk] : 0.f;
            int kb = idx >> 6, c = idx & 63;
            int gc = bn + c;
            Bs[kb][c] = (gc < Nn) ? Bm[(size_t)(k0 + kb) * Nn + gc] : 0.f;
        }
        __syncthreads();
        #pragma unroll
        for (int kk = 0; kk < 16; kk++) {
            float a[4], bb[4];
            #pragma unroll
            for (int i = 0; i < 4; i++) a[i]  = As[ty*4+i][kk];
            #pragma unroll
            for (int j = 0; j < 4; j++) bb[j] = Bs[kk][tx*4+j];
            #pragma unroll
            for (int i = 0; i < 4; i++)
                #pragma unroll
                for (int j = 0; j < 4; j++)
                    acc[i][j] += a[i] * bb[j];
        }
        __syncthreads();
    }
    #pragma unroll
    for (int i = 0; i < 4; i++) {
        int gr = bm + ty*4 + i;
        if (gr >= M) continue;
        #pragma unroll
        for (int j = 0; j < 4; j++) {
            int gc = bn + tx*4 + j;
            if (gc >= Nn) continue;
            C[(size_t)gr * Nn + gc] = __float2half(acc[i][j]);
        }
    }
}

// ---------------- launch ----------------
extern "C" void kernel_launch(void* const* d_in, const int* in_sizes, int n_in,
                              void* d_out, int out_size) {
    const float* x      = (const float*)d_in[0];
    const float* ctx    = (const float*)d_in[1];
    const float* w1_q   = (const float*)d_in[2];
    const float* w1_k   = (const float*)d_in[3];
    const float* w1_v   = (const float*)d_in[4];
    const float* w1_o   = (const float*)d_in[5];
    const float* b1_o   = (const float*)d_in[6];
    const float* w2_q   = (const float*)d_in[7];
    const float* w2_k   = (const float*)d_in[8];
    const float* w2_v   = (const float*)d_in[9];
    const float* w2_o   = (const float*)d_in[10];
    const float* b2_o   = (const float*)d_in[11];
    const float* ln1_g  = (const float*)d_in[12];
    const float* ln1_b  = (const float*)d_in[13];
    const float* ln2_g  = (const float*)d_in[14];
    const float* ln2_b  = (const float*)d_in[15];
    const float* ln3_g  = (const float*)d_in[16];
    const float* ln3_b  = (const float*)d_in[17];
    const float* ff_w1  = (const float*)d_in[18];
    const float* ff_b1  = (const float*)d_in[19];
    const float* ff_w2  = (const float*)d_in[20];
    const float* ff_b2  = (const float*)d_in[21];
    float* xbuf = (float*)d_out;

    __half *hh, *qkvh, *kh, *vh, *atth, *th, *wh;
    cudaGetSymbolAddress((void**)&hh,   g_hh);
    cudaGetSymbolAddress((void**)&qkvh, g_qkv);
    cudaGetSymbolAddress((void**)&kh,   g_kh);
    cudaGetSymbolAddress((void**)&vh,   g_vh);
    cudaGetSymbolAddress((void**)&atth, g_atth);
    cudaGetSymbolAddress((void**)&th,   g_th);
    cudaGetSymbolAddress((void**)&wh,   g_wh);

    cudaFuncSetAttribute(gemm_h<0>, cudaFuncAttributeMaxDynamicSharedMemorySize, GH_SMEM);
    cudaFuncSetAttribute(gemm_h<1>, cudaFuncAttributeMaxDynamicSharedMemorySize, GH_SMEM);
    cudaFuncSetAttribute(gemm_h<2>, cudaFuncAttributeMaxDynamicSharedMemorySize, GH_SMEM);
    cudaFuncSetAttribute(flash_h,     cudaFuncAttributeMaxDynamicSharedMemorySize, FLH_SMEM);
    cudaFuncSetAttribute(flash_cross, cudaFuncAttributeMaxDynamicSharedMemorySize, FLC_SMEM);

    dim3 gD(Dm/128, MROWS/128);
    dim3 gQKV(3*Dm/128, MROWS/128);
    dim3 gFF1(2*FFd/128, MROWS/128);
    dim3 gFlash(SEQ/128, Bq*Hh);
    dim3 tpb(32, 8);

    transpose_half6<<<dim3(Dm/32, Dm/32, 6), tpb>>>(
        w1_q, w1_k, w1_v, w1_o, w2_q, w2_o,
        wh+OWQKV, wh+OWQKV+1024*1024, wh+OWQKV+2*1024*1024,
        wh+OW1O, wh+OW2Q, wh+OW2O);
    transpose_geglu<<<dim3(2*FFd/32, Dm/32), tpb>>>(ff_w1, wh+OFW1, Dm,  2*FFd);
    transpose_half<<<dim3(Dm/32,  FFd/32),  tpb>>>(ff_w2, wh+OFW2, FFd, Dm);

    // ---- self attention ----
    ln_kernel<<<MROWS, 256>>>(x, ln1_g, ln1_b, hh);
    gemm_h<1><<<gQKV, 256, GH_SMEM>>>(hh, wh+OWQKV, nullptr, nullptr, qkvh, MROWS, 3*Dm, Dm);
    flash_h<<<gFlash, 256, FLH_SMEM>>>(qkvh, atth);
    gemm_h<0><<<gD, 256, GH_SMEM>>>(atth, wh+OW1O, b1_o, x, xbuf, MROWS, Dm, Dm);

    // ---- cross attention ----
    ln_kernel<<<MROWS, 256>>>(xbuf, ln2_g, ln2_b, hh);
    gemm_h<1><<<gD, 256, GH_SMEM>>>(hh, wh+OW2Q, nullptr, nullptr, atth, MROWS, Dm, Dm);
    dim3 gKV(Dm/64, (CROWS+63)/64, 2);
    gemm_kv_h<<<gKV, 256>>>(ctx, w2_k, w2_v, kh, vh, CROWS, DCx, Dm);
    flash_cross<<<gFlash, 256, FLC_SMEM>>>(atth, kh, vh, qkvh);
    gemm_h<0><<<gD, 256, GH_SMEM>>>(qkvh, wh+OW2O, b2_o, xbuf, xbuf, MROWS, Dm, Dm);

    // ---- GEGLU FFN ----
    ln_kernel<<<MROWS, 256>>>(xbuf, ln3_g, ln3_b, hh);
    gemm_h<2><<<gFF1, 256, GH_SMEM>>>(hh, wh+OFW1, ff_b1, nullptr, th, MROWS, 2*FFd, Dm);
    gemm_h<0><<<gD, 256, GH_SMEM>>>(th, wh+OFW2, ff_b2, xbuf, xbuf, MROWS, Dm, FFd);
}

// round 16
// speedup vs baseline: 1.4800x; 1.4800x over previous
#include <cuda_runtime.h>
#include <cuda_fp16.h>
#include <math.h>
#include <stdint.h>

#define Bq 2
#define SEQ 2048
#define Dm 1024
#define NCx 77
#define DCx 768
#define Hh 16
#define DHd 64
#define FFd 4096
#define SCALE_ATTN 0.125f
#define EPS_LN 1e-5f
#define MROWS (Bq*SEQ)          // 4096
#define CROWS (Bq*NCx)          // 154

// ---------------- scratch ----------------
__device__ __half g_hh[(size_t)MROWS*Dm];
__device__ __half g_qkv[(size_t)MROWS*3*Dm];
__device__ __half g_kh[(size_t)CROWS*Dm + 1024];
__device__ __half g_vh[(size_t)CROWS*Dm + 1024];
__device__ __half g_atth[(size_t)MROWS*Dm];
__device__ __half g_th[(size_t)MROWS*FFd];
__device__ __half g_wh[(size_t)18874368];        // transposed half weights [N,K]

#define OWQKV 0
#define OW1O 3145728
#define OW2Q 4194304
#define OW2O 5242880
#define OFW1 6291456
#define OFW2 14680064

// ---------------- helpers ----------------
__device__ __forceinline__ float ex2f(float x) {
    float y;
    asm("ex2.approx.f32 %0, %1;" : "=f"(y) : "f"(x));
    return y;
}
// pack two floats to a half2 fragment (lo in lower 16 bits) — matches __floats2half2_rn(lo,hi)
__device__ __forceinline__ uint32_t pack_h2(float lo, float hi) {
    uint32_t u;
    asm("cvt.rn.f16x2.f32 %0, %1, %2;" : "=r"(u) : "f"(hi), "f"(lo));
    return u;
}
__device__ __forceinline__ void mma_f16(float c[4],
                                        uint32_t a0, uint32_t a1, uint32_t a2, uint32_t a3,
                                        uint32_t b0, uint32_t b1) {
    asm volatile(
        "mma.sync.aligned.m16n8k16.row.col.f32.f16.f16.f32 "
        "{%0,%1,%2,%3}, {%4,%5,%6,%7}, {%8,%9}, {%0,%1,%2,%3};"
        : "+f"(c[0]), "+f"(c[1]), "+f"(c[2]), "+f"(c[3])
        : "r"(a0), "r"(a1), "r"(a2), "r"(a3), "r"(b0), "r"(b1));
}
__device__ __forceinline__ void ldsm4(uint32_t& r0, uint32_t& r1, uint32_t& r2, uint32_t& r3,
                                      uint32_t addr) {
    asm volatile("ldmatrix.sync.aligned.m8n8.x4.shared.b16 {%0,%1,%2,%3}, [%4];"
                 : "=r"(r0), "=r"(r1), "=r"(r2), "=r"(r3) : "r"(addr));
}
__device__ __forceinline__ void ldsm4t(uint32_t& r0, uint32_t& r1, uint32_t& r2, uint32_t& r3,
                                       uint32_t addr) {
    asm volatile("ldmatrix.sync.aligned.m8n8.x4.trans.shared.b16 {%0,%1,%2,%3}, [%4];"
                 : "=r"(r0), "=r"(r1), "=r"(r2), "=r"(r3) : "r"(addr));
}
__device__ __forceinline__ void cpa16(uint32_t dst, const void* src) {
    asm volatile("cp.async.cg.shared.global [%0], [%1], 16;" :: "r"(dst), "l"(src));
}
#define CP_COMMIT() asm volatile("cp.async.commit_group;")
#define CP_WAIT1()  asm volatile("cp.async.wait_group 1;")
#define CP_WAIT0()  asm volatile("cp.async.wait_group 0;")

// ---------------- weight transpose + fp16 convert ----------------
__global__ void transpose_half6(const float* s0, const float* s1, const float* s2,
                                const float* s3, const float* s4, const float* s5,
                                __half* d0, __half* d1, __half* d2,
                                __half* d3, __half* d4, __half* d5) {
    const float* src; __half* dst;
    switch (blockIdx.z) {
        case 0: src = s0; dst = d0; break;
        case 1: src = s1; dst = d1; break;
        case 2: src = s2; dst = d2; break;
        case 3: src = s3; dst = d3; break;
        case 4: src = s4; dst = d4; break;
        default: src = s5; dst = d5; break;
    }
    __shared__ float t[32][33];
    int bx = blockIdx.x * 32;
    int by = blockIdx.y * 32;
    int x = bx + threadIdx.x;
    #pragma unroll
    for (int i = 0; i < 32; i += 8) {
        int y = by + threadIdx.y + i;
        t[threadIdx.y + i][threadIdx.x] = src[(size_t)y * Dm + x];
    }
    __syncthreads();
    int kx = by + threadIdx.x;
    #pragma unroll
    for (int i = 0; i < 32; i += 8) {
        int ny = bx + threadIdx.y + i;
        dst[(size_t)ny * Dm + kx] = __float2half(t[threadIdx.x][threadIdx.y + i]);
    }
}
__global__ void transpose_half(const float* __restrict__ src, __half* __restrict__ dst,
                               int K, int N) {
    __shared__ float t[32][33];
    int bx = blockIdx.x * 32;
    int by = blockIdx.y * 32;
    int x = bx + threadIdx.x;
    #pragma unroll
    for (int i = 0; i < 32; i += 8) {
        int y = by + threadIdx.y + i;
        t[threadIdx.y + i][threadIdx.x] = src[(size_t)y * N + x];
    }
    __syncthreads();
    int kx = by + threadIdx.x;
    #pragma unroll
    for (int i = 0; i < 32; i += 8) {
        int ny = bx + threadIdx.y + i;
        dst[(size_t)ny * K + kx] = __float2half(t[threadIdx.x][threadIdx.y + i]);
    }
}
__global__ void transpose_geglu(const float* __restrict__ src, __half* __restrict__ dst,
                                int K, int N) {
    __shared__ float t[32][33];
    int bx = blockIdx.x * 32;
    int by = blockIdx.y * 32;
    int x = bx + threadIdx.x;
    #pragma unroll
    for (int i = 0; i < 32; i += 8) {
        int y = by + threadIdx.y + i;
        t[threadIdx.y + i][threadIdx.x] = src[(size_t)y * N + x];
    }
    __syncthreads();
    int kx = by + threadIdx.x;
    #pragma unroll
    for (int i = 0; i < 32; i += 8) {
        int ny = bx + threadIdx.y + i;
        int iny = (ny < FFd) ? (2*ny) : (2*(ny - FFd) + 1);
        dst[(size_t)iny * K + kx] = __float2half(t[threadIdx.x][threadIdx.y + i]);
    }
}

// ================= fp16 dense GEMM (ldmatrix, BK=64, 3-stage) ===============
#define ASH 72
#define HTILE (128*ASH)
#define GH_SMEM (3*2*HTILE*2)

template<int MODE>
__global__ __launch_bounds__(256, 2)
void gemm_h(const __half* __restrict__ A, const __half* __restrict__ Bt,
            const float* __restrict__ bias, const float* __restrict__ res,
            void* __restrict__ Cv, int M, int N, int K) {
    extern __shared__ __half smh[];
    __half* As = smh;
    __half* Bs = smh + 3*HTILE;
    int bm = blockIdx.y * 128, bn = blockIdx.x * 128;
    int tid = threadIdx.x, warp = tid >> 5, lane = tid & 31;
    int grp = lane >> 2, tig = lane & 3;
    int wm = (warp >> 2) * 64, wn = (warp & 3) * 32;
    int sel = lane >> 3, lrow = lane & 7;
    int a_r = (sel & 1) * 8 + lrow, a_c = (sel >> 1) * 8;
    int b_r = (sel >> 1) * 8 + lrow, b_c = (sel & 1) * 8;
    uint32_t sAu = (uint32_t)__cvta_generic_to_shared(As);
    uint32_t sBu = (uint32_t)__cvta_generic_to_shared(Bs);
    int niter = K >> 6;

    float acc[4][4][4] = {};

    auto loadTile = [&](int it, int buf) {
        int k0 = it * 64;
        #pragma unroll
        for (int i = 0; i < 4; i++) {
            int c = tid + i * 256;
            int row = c >> 3, kq = c & 7;
            cpa16(sAu + (uint32_t)(buf*HTILE + row*ASH + kq*8) * 2,
                  A + (size_t)(bm + row) * K + k0 + kq * 8);
            cpa16(sBu + (uint32_t)(buf*HTILE + row*ASH + kq*8) * 2,
                  Bt + (size_t)(bn + row) * K + k0 + kq * 8);
        }
        CP_COMMIT();
    };

    loadTile(0, 0);
    loadTile(1, 1);

    for (int it = 0; it < niter; ++it) {
        CP_WAIT1();
        __syncthreads();
        if (it + 2 < niter) loadTile(it + 2, (it + 2) % 3);
        else CP_COMMIT();

        uint32_t Abu = sAu + (uint32_t)((it % 3) * HTILE) * 2;
        uint32_t Bbu = sBu + (uint32_t)((it % 3) * HTILE) * 2;
        #pragma unroll
        for (int ks = 0; ks < 64; ks += 16) {
            uint32_t af[4][4], bf[4][2];
            #pragma unroll
            for (int mf = 0; mf < 4; mf++) {
                uint32_t ad = Abu + (uint32_t)((wm + mf*16 + a_r) * ASH + ks + a_c) * 2;
                ldsm4(af[mf][0], af[mf][1], af[mf][2], af[mf][3], ad);
            }
            #pragma unroll
            for (int np = 0; np < 2; np++) {
                uint32_t bd = Bbu + (uint32_t)((wn + np*16 + b_r) * ASH + ks + b_c) * 2;
                ldsm4(bf[2*np][0], bf[2*np][1], bf[2*np+1][0], bf[2*np+1][1], bd);
            }
            #pragma unroll
            for (int mf = 0; mf < 4; mf++)
                #pragma unroll
                for (int nf = 0; nf < 4; nf++)
                    mma_f16(acc[mf][nf], af[mf][0], af[mf][1], af[mf][2], af[mf][3],
                            bf[nf][0], bf[nf][1]);
        }
    }

    #pragma unroll
    for (int mf = 0; mf < 4; mf++) {
        #pragma unroll
        for (int nf = 0; nf < 4; nf++) {
            int r = bm + wm + mf*16 + grp;
            int c = bn + wn + nf*8 + tig*2;
            float2 v0 = make_float2(acc[mf][nf][0], acc[mf][nf][1]);
            float2 v1 = make_float2(acc[mf][nf][2], acc[mf][nf][3]);
            if (MODE == 2) {
                int j = c >> 1;
                float bv = bias[j], bg = bias[FFd + j];
                float val0 = v0.x + bv, gat0 = v0.y + bg;
                float val1 = v1.x + bv, gat1 = v1.y + bg;
                float o0 = val0 * (0.5f * gat0 * (1.f + erff(gat0 * 0.70710678118654752f)));
                float o1 = val1 * (0.5f * gat1 * (1.f + erff(gat1 * 0.70710678118654752f)));
                __half* C = (__half*)Cv;
                C[(size_t)r * FFd + j]     = __float2half(o0);
                C[(size_t)(r+8) * FFd + j] = __float2half(o1);
            } else {
                if (bias) {
                    float2 bb = *(const float2*)(bias + c);
                    v0.x += bb.x; v0.y += bb.y; v1.x += bb.x; v1.y += bb.y;
                }
                if (MODE == 0 && res) {
                    float2 r0 = *(const float2*)(res + (size_t)r * N + c);
                    float2 r1 = *(const float2*)(res + (size_t)(r+8) * N + c);
                    v0.x += r0.x; v0.y += r0.y; v1.x += r1.x; v1.y += r1.y;
                }
                if (MODE == 1) {
                    __half* C = (__half*)Cv;
                    *(__half2*)(C + (size_t)r * N + c)     = __floats2half2_rn(v0.x, v0.y);
                    *(__half2*)(C + (size_t)(r+8) * N + c) = __floats2half2_rn(v1.x, v1.y);
                } else {
                    float* C = (float*)Cv;
                    *(float2*)(C + (size_t)r * N + c)     = v0;
                    *(float2*)(C + (size_t)(r+8) * N + c) = v1;
                }
            }
        }
    }
}

// ================= fp16 flash attention (register-P + double-buffered KV) ===
#define QSH 72
#define FTILE (128*QSH)
#define FLH_SMEM (5*FTILE*2)     // Q + 2*K + 2*V

__global__ __launch_bounds__(256, 2)
void flash_h(const __half* __restrict__ qkv, __half* __restrict__ o) {
    extern __shared__ __half smf[];
    __half* Qs = smf;
    uint32_t Qsu = (uint32_t)__cvta_generic_to_shared(Qs);
    uint32_t Ku[2] = { Qsu + (uint32_t)FTILE*2,   Qsu + (uint32_t)(2*FTILE)*2 };
    uint32_t Vu[2] = { Qsu + (uint32_t)(3*FTILE)*2, Qsu + (uint32_t)(4*FTILE)*2 };

    const int ldq = 3*Dm;
    int qt = blockIdx.x, bh = blockIdx.y;
    int b = bh >> 4, h = bh & 15;
    int tid = threadIdx.x, warp = tid >> 5, lane = tid & 31;
    int grp = lane >> 2, tig = lane & 3;
    int sel = lane >> 3, lrow = lane & 7;
    int a_r = (sel & 1) * 8 + lrow, a_c = (sel >> 1) * 8;
    int b_r = (sel >> 1) * 8 + lrow, b_c = (sel & 1) * 8;

    const __half* qb = qkv + ((size_t)b*SEQ + qt*128) * ldq + h*DHd;
    const __half* kb = qkv + (size_t)b*SEQ*ldq + Dm + h*DHd;
    const __half* vb = qkv + (size_t)b*SEQ*ldq + 2*Dm + h*DHd;

    {
        int row = tid >> 1, part = tid & 1;
        const float4* s4 = (const float4*)(qb + (size_t)row * ldq + part*32);
        float4* d4 = (float4*)(Qs + row*QSH + part*32);
        #pragma unroll
        for (int i = 0; i < 4; i++) d4[i] = s4[i];
    }

    auto loadKV = [&](int kv0, int buf) {
        #pragma unroll
        for (int i = 0; i < 4; i++) {
            int c = tid + i * 256;
            int row = c >> 3, kq = c & 7;
            cpa16(Ku[buf] + (uint32_t)(row*QSH + kq*8) * 2,
                  kb + (size_t)(kv0 + row) * ldq + kq * 8);
            cpa16(Vu[buf] + (uint32_t)(row*QSH + kq*8) * 2,
                  vb + (size_t)(kv0 + row) * ldq + kq * 8);
        }
        CP_COMMIT();
    };
    loadKV(0, 0);

    __syncthreads();
    uint32_t qf[4][4];
    {
        const __half* p = Qs + (warp*16 + grp) * QSH;
        #pragma unroll
        for (int ksi = 0; ksi < 4; ksi++) {
            qf[ksi][0] = *(const uint32_t*)(p + ksi*16 + tig*2);
            qf[ksi][1] = *(const uint32_t*)(p + 8*QSH + ksi*16 + tig*2);
            qf[ksi][2] = *(const uint32_t*)(p + ksi*16 + tig*2 + 8);
            qf[ksi][3] = *(const uint32_t*)(p + 8*QSH + ksi*16 + tig*2 + 8);
        }
    }

    float oacc[8][4] = {};
    float m0 = -1e30f, m1 = -1e30f, l0 = 0.f, l1 = 0.f;
    const float Csc = SCALE_ATTN * 1.4426950408889634f;

    for (int it = 0; it < SEQ/128; ++it) {
        int buf = it & 1;
        CP_WAIT0();
        __syncthreads();
        if (it + 1 < SEQ/128) loadKV((it + 1) * 128, buf ^ 1);

        float sacc[16][4] = {};
        #pragma unroll
        for (int ksi = 0; ksi < 4; ksi++) {
            #pragma unroll
            for (int np = 0; np < 8; np++) {
                uint32_t kd = Ku[buf] + (uint32_t)((np*16 + b_r) * QSH + ksi*16 + b_c) * 2;
                uint32_t b00, b01, b10, b11;
                ldsm4(b00, b01, b10, b11, kd);
                mma_f16(sacc[2*np],   qf[ksi][0], qf[ksi][1], qf[ksi][2], qf[ksi][3], b00, b01);
                mma_f16(sacc[2*np+1], qf[ksi][0], qf[ksi][1], qf[ksi][2], qf[ksi][3], b10, b11);
            }
        }
        float mx0 = -1e30f, mx1 = -1e30f;
        #pragma unroll
        for (int nf = 0; nf < 16; nf++) {
            sacc[nf][0] *= Csc; sacc[nf][1] *= Csc; sacc[nf][2] *= Csc; sacc[nf][3] *= Csc;
            mx0 = fmaxf(mx0, fmaxf(sacc[nf][0], sacc[nf][1]));
            mx1 = fmaxf(mx1, fmaxf(sacc[nf][2], sacc[nf][3]));
        }
        mx0 = fmaxf(mx0, __shfl_xor_sync(0xffffffffu, mx0, 1));
        mx0 = fmaxf(mx0, __shfl_xor_sync(0xffffffffu, mx0, 2));
        mx1 = fmaxf(mx1, __shfl_xor_sync(0xffffffffu, mx1, 1));
        mx1 = fmaxf(mx1, __shfl_xor_sync(0xffffffffu, mx1, 2));
        float mn0 = fmaxf(m0, mx0), mn1 = fmaxf(m1, mx1);
        float sc0 = ex2f(m0 - mn0), sc1 = ex2f(m1 - mn1);
        float sum0 = 0.f, sum1 = 0.f;
        uint32_t ph[16][2];
        #pragma unroll
        for (int nf = 0; nf < 16; nf++) {
            float p0 = ex2f(sacc[nf][0] - mn0);
            float p1 = ex2f(sacc[nf][1] - mn0);
            float p2 = ex2f(sacc[nf][2] - mn1);
            float p3 = ex2f(sacc[nf][3] - mn1);
            sum0 += p0 + p1; sum1 += p2 + p3;
            ph[nf][0] = pack_h2(p0, p1);
            ph[nf][1] = pack_h2(p2, p3);
        }
        sum0 += __shfl_xor_sync(0xffffffffu, sum0, 1);
        sum0 += __shfl_xor_sync(0xffffffffu, sum0, 2);
        sum1 += __shfl_xor_sync(0xffffffffu, sum1, 1);
        sum1 += __shfl_xor_sync(0xffffffffu, sum1, 2);
        l0 = l0 * sc0 + sum0;  l1 = l1 * sc1 + sum1;
        m0 = mn0;  m1 = mn1;
        #pragma unroll
        for (int nf = 0; nf < 8; nf++) {
            oacc[nf][0] *= sc0; oacc[nf][1] *= sc0;
            oacc[nf][2] *= sc1; oacc[nf][3] *= sc1;
        }

        #pragma unroll
        for (int ks = 0; ks < 8; ks++) {
            uint32_t a0 = ph[2*ks][0], a1 = ph[2*ks][1];
            uint32_t a2 = ph[2*ks+1][0], a3 = ph[2*ks+1][1];
            #pragma unroll
            for (int np = 0; np < 4; np++) {
                uint32_t vd = Vu[buf] + (uint32_t)((ks*16 + a_r) * QSH + np*16 + a_c) * 2;
                uint32_t b00, b01, b10, b11;
                ldsm4t(b00, b01, b10, b11, vd);
                mma_f16(oacc[2*np],   a0, a1, a2, a3, b00, b01);
                mma_f16(oacc[2*np+1], a0, a1, a2, a3, b10, b11);
            }
        }
    }

    float i0 = 1.f / l0, i1 = 1.f / l1;
    __half* ob = o + ((size_t)b*SEQ + qt*128 + warp*16) * Dm + h*DHd;
    #pragma unroll
    for (int nf = 0; nf < 8; nf++) {
        int c = nf*8 + tig*2;
        *(__half2*)(ob + (size_t)grp * Dm + c) =
            __floats2half2_rn(oacc[nf][0]*i0, oacc[nf][1]*i0);
        *(__half2*)(ob + (size_t)(grp+8) * Dm + c) =
            __floats2half2_rn(oacc[nf][2]*i1, oacc[nf][3]*i1);
    }
}

// ================= fp16 cross-attention (single KV tile, nk=77) =============
#define CKROWS 80
#define FLC_SMEM ((128*QSH + 2*CKROWS*QSH)*2)

__global__ __launch_bounds__(256, 2)
void flash_cross(const __half* __restrict__ q, const __half* __restrict__ k,
                 const __half* __restrict__ v, __half* __restrict__ o) {
    extern __shared__ __half smc[];
    __half* Qs = smc;
    __half* Ks = Qs + 128*QSH;
    __half* Vs = Ks + CKROWS*QSH;
    uint32_t Vsu = (uint32_t)__cvta_generic_to_shared(Vs);

    int qt = blockIdx.x, bh = blockIdx.y;
    int b = bh >> 4, h = bh & 15;
    int tid = threadIdx.x, warp = tid >> 5, lane = tid & 31;
    int grp = lane >> 2, tig = lane & 3;
    int sel = lane >> 3, lrow = lane & 7;
    int a_r = (sel & 1) * 8 + lrow, a_c = (sel >> 1) * 8;

    const __half* qb = q + ((size_t)b*SEQ + qt*128) * Dm + h*DHd;
    const __half* kb = k + (size_t)b*NCx*Dm + h*DHd;
    const __half* vb = v + (size_t)b*NCx*Dm + h*DHd;

    {
        int row = tid >> 1, part = tid & 1;
        const float4* s4 = (const float4*)(qb + (size_t)row * Dm + part*32);
        float4* d4 = (float4*)(Qs + row*QSH + part*32);
        #pragma unroll
        for (int i = 0; i < 4; i++) d4[i] = s4[i];
    }
    for (int rr = tid; rr < CKROWS*2; rr += 256) {
        int row = rr >> 1, part = rr & 1;
        float4* dk = (float4*)(Ks + row*QSH + part*32);
        float4* dv = (float4*)(Vs + row*QSH + part*32);
        if (row < NCx) {
            const float4* sk = (const float4*)(kb + (size_t)row * Dm + part*32);
            const float4* sv = (const float4*)(vb + (size_t)row * Dm + part*32);
            #pragma unroll
            for (int i = 0; i < 4; i++) { dk[i] = sk[i]; dv[i] = sv[i]; }
        } else {
            float4 z = make_float4(0.f,0.f,0.f,0.f);
            #pragma unroll
            for (int i = 0; i < 4; i++) { dk[i] = z; dv[i] = z; }
        }
    }
    __syncthreads();

    uint32_t qf[4][4];
    {
        const __half* p = Qs + (warp*16 + grp) * QSH;
        #pragma unroll
        for (int ksi = 0; ksi < 4; ksi++) {
            qf[ksi][0] = *(const uint32_t*)(p + ksi*16 + tig*2);
            qf[ksi][1] = *(const uint32_t*)(p + 8*QSH + ksi*16 + tig*2);
            qf[ksi][2] = *(const uint32_t*)(p + ksi*16 + tig*2 + 8);
            qf[ksi][3] = *(const uint32_t*)(p + 8*QSH + ksi*16 + tig*2 + 8);
        }
    }

    const float Csc = SCALE_ATTN * 1.4426950408889634f;

    float sacc[10][4] = {};
    #pragma unroll
    for (int ksi = 0; ksi < 4; ksi++) {
        #pragma unroll
        for (int nf = 0; nf < 10; nf++) {
            const __half* kp = Ks + (nf*8 + grp) * QSH + ksi*16;
            uint32_t b0 = *(const uint32_t*)(kp + tig*2);
            uint32_t b1 = *(const uint32_t*)(kp + tig*2 + 8);
            mma_f16(sacc[nf], qf[ksi][0], qf[ksi][1], qf[ksi][2], qf[ksi][3], b0, b1);
        }
    }
    float mx0 = -1e30f, mx1 = -1e30f;
    #pragma unroll
    for (int nf = 0; nf < 10; nf++) {
        int c0 = nf*8 + tig*2, c1 = c0 + 1;
        sacc[nf][0] = (c0 < NCx) ? sacc[nf][0]*Csc : -1e30f;
        sacc[nf][1] = (c1 < NCx) ? sacc[nf][1]*Csc : -1e30f;
        sacc[nf][2] = (c0 < NCx) ? sacc[nf][2]*Csc : -1e30f;
        sacc[nf][3] = (c1 < NCx) ? sacc[nf][3]*Csc : -1e30f;
        mx0 = fmaxf(mx0, fmaxf(sacc[nf][0], sacc[nf][1]));
        mx1 = fmaxf(mx1, fmaxf(sacc[nf][2], sacc[nf][3]));
    }
    mx0 = fmaxf(mx0, __shfl_xor_sync(0xffffffffu, mx0, 1));
    mx0 = fmaxf(mx0, __shfl_xor_sync(0xffffffffu, mx0, 2));
    mx1 = fmaxf(mx1, __shfl_xor_sync(0xffffffffu, mx1, 1));
    mx1 = fmaxf(mx1, __shfl_xor_sync(0xffffffffu, mx1, 2));

    float sum0 = 0.f, sum1 = 0.f;
    uint32_t ph[10][2];
    #pragma unroll
    for (int nf = 0; nf < 10; nf++) {
        float p0 = ex2f(sacc[nf][0] - mx0);
        float p1 = ex2f(sacc[nf][1] - mx0);
        float p2 = ex2f(sacc[nf][2] - mx1);
        float p3 = ex2f(sacc[nf][3] - mx1);
        sum0 += p0 + p1; sum1 += p2 + p3;
        ph[nf][0] = pack_h2(p0, p1);
        ph[nf][1] = pack_h2(p2, p3);
    }
    sum0 += __shfl_xor_sync(0xffffffffu, sum0, 1);
    sum0 += __shfl_xor_sync(0xffffffffu, sum0, 2);
    sum1 += __shfl_xor_sync(0xffffffffu, sum1, 1);
    sum1 += __shfl_xor_sync(0xffffffffu, sum1, 2);

    float oacc[8][4] = {};
    #pragma unroll
    for (int ks = 0; ks < 5; ks++) {
        uint32_t a0 = ph[2*ks][0], a1 = ph[2*ks][1];
        uint32_t a2 = ph[2*ks+1][0], a3 = ph[2*ks+1][1];
        #pragma unroll
        for (int np = 0; np < 4; np++) {
            uint32_t vd = Vsu + (uint32_t)((ks*16 + a_r) * QSH + np*16 + a_c) * 2;
            uint32_t b00, b01, b10, b11;
            ldsm4t(b00, b01, b10, b11, vd);
            mma_f16(oacc[2*np],   a0, a1, a2, a3, b00, b01);
            mma_f16(oacc[2*np+1], a0, a1, a2, a3, b10, b11);
        }
    }

    float i0 = 1.f / sum0, i1 = 1.f / sum1;
    __half* ob = o + ((size_t)b*SEQ + qt*128 + warp*16) * Dm + h*DHd;
    #pragma unroll
    for (int nf = 0; nf < 8; nf++) {
        int c = nf*8 + tig*2;
        *(__half2*)(ob + (size_t)grp * Dm + c) =
            __floats2half2_rn(oacc[nf][0]*i0, oacc[nf][1]*i0);
        *(__half2*)(ob + (size_t)(grp+8) * Dm + c) =
            __floats2half2_rn(oacc[nf][2]*i1, oacc[nf][3]*i1);
    }
}

// ---------------- layernorm: single-pass float4 + warp shuffle ----------------
__global__ __launch_bounds__(256)
void ln_kernel(const float* __restrict__ x, const float* __restrict__ g,
               const float* __restrict__ b, __half* __restrict__ out) {
    int row = blockIdx.x;
    int tid = threadIdx.x, warp = tid >> 5, lane = tid & 31;
    const float4* xr = (const float4*)(x + (size_t)row * Dm);
    float4 v = xr[tid];
    float s  = v.x + v.y + v.z + v.w;
    float ss = v.x*v.x + v.y*v.y + v.z*v.z + v.w*v.w;
    #pragma unroll
    for (int o = 16; o > 0; o >>= 1) {
        s  += __shfl_xor_sync(0xffffffffu, s,  o);
        ss += __shfl_xor_sync(0xffffffffu, ss, o);
    }
    __shared__ float ws[8], wss[8];
    if (lane == 0) { ws[warp] = s; wss[warp] = ss; }
    __syncthreads();
    float ts = 0.f, tss = 0.f;
    #pragma unroll
    for (int i = 0; i < 8; i++) { ts += ws[i]; tss += wss[i]; }
    float mu  = ts * (1.0f / Dm);
    float var = tss * (1.0f / Dm) - mu * mu;
    float inv = rsqrtf(var + EPS_LN);
    float4 gv = ((const float4*)g)[tid];
    float4 bv = ((const float4*)b)[tid];
    float o0 = (v.x - mu) * inv * gv.x + bv.x;
    float o1 = (v.y - mu) * inv * gv.y + bv.y;
    float o2 = (v.z - mu) * inv * gv.z + bv.z;
    float o3 = (v.w - mu) * inv * gv.w + bv.w;
    __half2* orow = (__half2*)(out + (size_t)row * Dm) + tid * 2;
    orow[0] = __floats2half2_rn(o0, o1);
    orow[1] = __floats2half2_rn(o2, o3);
}

__global__ void gemm_kv_h(const float* __restrict__ A,
                          const float* __restrict__ Wk, const float* __restrict__ Wv,
                          __half* __restrict__ Ck, __half* __restrict__ Cv,
                          int M, int K, int Nn) {
    __shared__ float As[64][17];
    __shared__ float Bs[16][64];
    const float* Bm = (blockIdx.z == 0) ? Wk : Wv;
    __half* C = (blockIdx.z == 0) ? Ck : Cv;
    int bm = blockIdx.y * 64, bn = blockIdx.x * 64;
    int tx = threadIdx.x & 15, ty = threadIdx.x >> 4;
    float acc[4][4] = {};
    for (int k0 = 0; k0 < K; k0 += 16) {
        #pragma unroll
        for (int i = 0; i < 4; i++) {
            int idx = threadIdx.x + i * 256;
            int r = idx >> 4, kk = idx & 15;
            int gr = bm + r;
            As[r][kk] = (gr < M) ? A[(size_t)gr * K + k0 + kk] : 0.f;
            int kb = idx >> 6, c = idx & 63;
            int gc = bn + c;
            Bs[kb][c] = (gc < Nn) ? Bm[(size_t)(k0 + kb) * Nn + gc] : 0.f;
        }
        __syncthreads();
        #pragma unroll
        for (int kk = 0; kk < 16; kk++) {
            float a[4], bb[4];
            #pragma unroll
            for (int i = 0; i < 4; i++) a[i]  = As[ty*4+i][kk];
            #pragma unroll
            for (int j = 0; j < 4; j++) bb[j] = Bs[kk][tx*4+j];
            #pragma unroll
            for (int i = 0; i < 4; i++)
                #pragma unroll
                for (int j = 0; j < 4; j++)
                    acc[i][j] += a[i] * bb[j];
        }
        __syncthreads();
    }
    #pragma unroll
    for (int i = 0; i < 4; i++) {
        int gr = bm + ty*4 + i;
        if (gr >= M) continue;
        #pragma unroll
        for (int j = 0; j < 4; j++) {
            int gc = bn + tx*4 + j;
            if (gc >= Nn) continue;
            C[(size_t)gr * Nn + gc] = __float2half(acc[i][j]);
        }
    }
}

// ---------------- launch ----------------
extern "C" void kernel_launch(void* const* d_in, const int* in_sizes, int n_in,
                              void* d_out, int out_size) {
    const float* x      = (const float*)d_in[0];
    const float* ctx    = (const float*)d_in[1];
    const float* w1_q   = (const float*)d_in[2];
    const float* w1_k   = (const float*)d_in[3];
    const float* w1_v   = (const float*)d_in[4];
    const float* w1_o   = (const float*)d_in[5];
    const float* b1_o   = (const float*)d_in[6];
    const float* w2_q   = (const float*)d_in[7];
    const float* w2_k   = (const float*)d_in[8];
    const float* w2_v   = (const float*)d_in[9];
    const float* w2_o   = (const float*)d_in[10];
    const float* b2_o   = (const float*)d_in[11];
    const float* ln1_g  = (const float*)d_in[12];
    const float* ln1_b  = (const float*)d_in[13];
    const float* ln2_g  = (const float*)d_in[14];
    const float* ln2_b  = (const float*)d_in[15];
    const float* ln3_g  = (const float*)d_in[16];
    const float* ln3_b  = (const float*)d_in[17];
    const float* ff_w1  = (const float*)d_in[18];
    const float* ff_b1  = (const float*)d_in[19];
    const float* ff_w2  = (const float*)d_in[20];
    const float* ff_b2  = (const float*)d_in[21];
    float* xbuf = (float*)d_out;

    __half *hh, *qkvh, *kh, *vh, *atth, *th, *wh;
    cudaGetSymbolAddress((void**)&hh,   g_hh);
    cudaGetSymbolAddress((void**)&qkvh, g_qkv);
    cudaGetSymbolAddress((void**)&kh,   g_kh);
    cudaGetSymbolAddress((void**)&vh,   g_vh);
    cudaGetSymbolAddress((void**)&atth, g_atth);
    cudaGetSymbolAddress((void**)&th,   g_th);
    cudaGetSymbolAddress((void**)&wh,   g_wh);

    cudaFuncSetAttribute(gemm_h<0>, cudaFuncAttributeMaxDynamicSharedMemorySize, GH_SMEM);
    cudaFuncSetAttribute(gemm_h<1>, cudaFuncAttributeMaxDynamicSharedMemorySize, GH_SMEM);
    cudaFuncSetAttribute(gemm_h<2>, cudaFuncAttributeMaxDynamicSharedMemorySize, GH_SMEM);
    cudaFuncSetAttribute(flash_h,     cudaFuncAttributeMaxDynamicSharedMemorySize, FLH_SMEM);
    cudaFuncSetAttribute(flash_cross, cudaFuncAttributeMaxDynamicSharedMemorySize, FLC_SMEM);

    dim3 gD(Dm/128, MROWS/128);
    dim3 gQKV(3*Dm/128, MROWS/128);
    dim3 gFF1(2*FFd/128, MROWS/128);
    dim3 gFlash(SEQ/128, Bq*Hh);
    dim3 tpb(32, 8);

    transpose_half6<<<dim3(Dm/32, Dm/32, 6), tpb>>>(
        w1_q, w1_k, w1_v, w1_o, w2_q, w2_o,
        wh+OWQKV, wh+OWQKV+1024*1024, wh+OWQKV+2*1024*1024,
        wh+OW1O, wh+OW2Q, wh+OW2O);
    transpose_geglu<<<dim3(2*FFd/32, Dm/32), tpb>>>(ff_w1, wh+OFW1, Dm,  2*FFd);
    transpose_half<<<dim3(Dm/32,  FFd/32),  tpb>>>(ff_w2, wh+OFW2, FFd, Dm);

    // ---- self attention ----
    ln_kernel<<<MROWS, 256>>>(x, ln1_g, ln1_b, hh);
    gemm_h<1><<<gQKV, 256, GH_SMEM>>>(hh, wh+OWQKV, nullptr, nullptr, qkvh, MROWS, 3*Dm, Dm);
    flash_h<<<gFlash, 256, FLH_SMEM>>>(qkvh, atth);
    gemm_h<0><<<gD, 256, GH_SMEM>>>(atth, wh+OW1O, b1_o, x, xbuf, MROWS, Dm, Dm);

    // ---- cross attention ----
    ln_kernel<<<MROWS, 256>>>(xbuf, ln2_g, ln2_b, hh);
    gemm_h<1><<<gD, 256, GH_SMEM>>>(hh, wh+OW2Q, nullptr, nullptr, atth, MROWS, Dm, Dm);
    dim3 gKV(Dm/64, (CROWS+63)/64, 2);
    gemm_kv_h<<<gKV, 256>>>(ctx, w2_k, w2_v, kh, vh, CROWS, DCx, Dm);
    flash_cross<<<gFlash, 256, FLC_SMEM>>>(atth, kh, vh, qkvh);
    gemm_h<0><<<gD, 256, GH_SMEM>>>(qkvh, wh+OW2O, b2_o, xbuf, xbuf, MROWS, Dm, Dm);

    // ---- GEGLU FFN ----
    ln_kernel<<<MROWS, 256>>>(xbuf, ln3_g, ln3_b, hh);
    gemm_h<2><<<gFF1, 256, GH_SMEM>>>(hh, wh+OFW1, ff_b1, nullptr, th, MROWS, 2*FFd, Dm);
    gemm_h<0><<<gD, 256, GH_SMEM>>>(th, wh+OFW2, ff_b2, xbuf, xbuf, MROWS, Dm, FFd);
}

// round 17
// speedup vs baseline: 1.5470x; 1.0452x over previous
#include <cuda_runtime.h>
#include <cuda_fp16.h>
#include <math.h>
#include <stdint.h>

#define Bq 2
#define SEQ 2048
#define Dm 1024
#define NCx 77
#define DCx 768
#define Hh 16
#define DHd 64
#define FFd 4096
#define SCALE_ATTN 0.125f
#define EPS_LN 1e-5f
#define MROWS (Bq*SEQ)          // 4096
#define CROWS (Bq*NCx)          // 154
#define CPAD 256                // padded cross rows (multiple of 128)

// ---------------- scratch ----------------
__device__ __half g_hh[(size_t)MROWS*Dm];
__device__ __half g_qkv[(size_t)MROWS*3*Dm];
__device__ __half g_ctxh[(size_t)CPAD*DCx];
__device__ __half g_kvh[(size_t)CPAD*2*Dm];
__device__ __half g_atth[(size_t)MROWS*Dm];
__device__ __half g_th[(size_t)MROWS*FFd];
__device__ __half g_wh[(size_t)20447232];        // transposed half weights [N,K]

#define OWQKV 0
#define OW1O 3145728
#define OW2Q 4194304
#define OW2O 5242880
#define OFW1 6291456
#define OFW2 14680064
#define OKV  18874368            // w2_k^T [1024,768] then w2_v^T [1024,768]

// ---------------- helpers ----------------
__device__ __forceinline__ float ex2f(float x) {
    float y;
    asm("ex2.approx.f32 %0, %1;" : "=f"(y) : "f"(x));
    return y;
}
// pack two floats to a half2 fragment (lo in lower 16 bits) — matches __floats2half2_rn(lo,hi)
__device__ __forceinline__ uint32_t pack_h2(float lo, float hi) {
    uint32_t u;
    asm("cvt.rn.f16x2.f32 %0, %1, %2;" : "=r"(u) : "f"(hi), "f"(lo));
    return u;
}
__device__ __forceinline__ void mma_f16(float c[4],
                                        uint32_t a0, uint32_t a1, uint32_t a2, uint32_t a3,
                                        uint32_t b0, uint32_t b1) {
    asm volatile(
        "mma.sync.aligned.m16n8k16.row.col.f32.f16.f16.f32 "
        "{%0,%1,%2,%3}, {%4,%5,%6,%7}, {%8,%9}, {%0,%1,%2,%3};"
        : "+f"(c[0]), "+f"(c[1]), "+f"(c[2]), "+f"(c[3])
        : "r"(a0), "r"(a1), "r"(a2), "r"(a3), "r"(b0), "r"(b1));
}
__device__ __forceinline__ void ldsm4(uint32_t& r0, uint32_t& r1, uint32_t& r2, uint32_t& r3,
                                      uint32_t addr) {
    asm volatile("ldmatrix.sync.aligned.m8n8.x4.shared.b16 {%0,%1,%2,%3}, [%4];"
                 : "=r"(r0), "=r"(r1), "=r"(r2), "=r"(r3) : "r"(addr));
}
__device__ __forceinline__ void ldsm4t(uint32_t& r0, uint32_t& r1, uint32_t& r2, uint32_t& r3,
                                       uint32_t addr) {
    asm volatile("ldmatrix.sync.aligned.m8n8.x4.trans.shared.b16 {%0,%1,%2,%3}, [%4];"
                 : "=r"(r0), "=r"(r1), "=r"(r2), "=r"(r3) : "r"(addr));
}
__device__ __forceinline__ void cpa16(uint32_t dst, const void* src) {
    asm volatile("cp.async.cg.shared.global [%0], [%1], 16;" :: "r"(dst), "l"(src));
}
#define CP_COMMIT() asm volatile("cp.async.commit_group;")
#define CP_WAIT1()  asm volatile("cp.async.wait_group 1;")
#define CP_WAIT0()  asm volatile("cp.async.wait_group 0;")

// ---------------- weight transpose + fp16 convert ----------------
__global__ void transpose_half6(const float* s0, const float* s1, const float* s2,
                                const float* s3, const float* s4, const float* s5,
                                __half* d0, __half* d1, __half* d2,
                                __half* d3, __half* d4, __half* d5) {
    const float* src; __half* dst;
    switch (blockIdx.z) {
        case 0: src = s0; dst = d0; break;
        case 1: src = s1; dst = d1; break;
        case 2: src = s2; dst = d2; break;
        case 3: src = s3; dst = d3; break;
        case 4: src = s4; dst = d4; break;
        default: src = s5; dst = d5; break;
    }
    __shared__ float t[32][33];
    int bx = blockIdx.x * 32;
    int by = blockIdx.y * 32;
    int x = bx + threadIdx.x;
    #pragma unroll
    for (int i = 0; i < 32; i += 8) {
        int y = by + threadIdx.y + i;
        t[threadIdx.y + i][threadIdx.x] = src[(size_t)y * Dm + x];
    }
    __syncthreads();
    int kx = by + threadIdx.x;
    #pragma unroll
    for (int i = 0; i < 32; i += 8) {
        int ny = bx + threadIdx.y + i;
        dst[(size_t)ny * Dm + kx] = __float2half(t[threadIdx.x][threadIdx.y + i]);
    }
}
__global__ void transpose_half(const float* __restrict__ src, __half* __restrict__ dst,
                               int K, int N) {
    __shared__ float t[32][33];
    int bx = blockIdx.x * 32;
    int by = blockIdx.y * 32;
    int x = bx + threadIdx.x;
    #pragma unroll
    for (int i = 0; i < 32; i += 8) {
        int y = by + threadIdx.y + i;
        t[threadIdx.y + i][threadIdx.x] = src[(size_t)y * N + x];
    }
    __syncthreads();
    int kx = by + threadIdx.x;
    #pragma unroll
    for (int i = 0; i < 32; i += 8) {
        int ny = bx + threadIdx.y + i;
        dst[(size_t)ny * K + kx] = __float2half(t[threadIdx.x][threadIdx.y + i]);
    }
}
__global__ void transpose_geglu(const float* __restrict__ src, __half* __restrict__ dst,
                                int K, int N) {
    __shared__ float t[32][33];
    int bx = blockIdx.x * 32;
    int by = blockIdx.y * 32;
    int x = bx + threadIdx.x;
    #pragma unroll
    for (int i = 0; i < 32; i += 8) {
        int y = by + threadIdx.y + i;
        t[threadIdx.y + i][threadIdx.x] = src[(size_t)y * N + x];
    }
    __syncthreads();
    int kx = by + threadIdx.x;
    #pragma unroll
    for (int i = 0; i < 32; i += 8) {
        int ny = bx + threadIdx.y + i;
        int iny = (ny < FFd) ? (2*ny) : (2*(ny - FFd) + 1);
        dst[(size_t)iny * K + kx] = __float2half(t[threadIdx.x][threadIdx.y + i]);
    }
}
// ctx fp32 [CROWS, DCx] -> half [CPAD, DCx] with zero pad rows
__global__ void ctx_to_half(const float* __restrict__ ctx, __half* __restrict__ dst) {
    int i = blockIdx.x * blockDim.x + threadIdx.x;   // over CPAD*DCx/2 half2
    if (i >= CPAD * DCx / 2) return;
    int row = i / (DCx/2);
    if (row < CROWS) {
        float2 v = ((const float2*)ctx)[i];
        ((__half2*)dst)[i] = __floats2half2_rn(v.x, v.y);
    } else {
        ((__half2*)dst)[i] = __floats2half2_rn(0.f, 0.f);
    }
}

// ================= fp16 dense GEMM (ldmatrix, BK=64, 3-stage) ===============
#define ASH 72
#define HTILE (128*ASH)
#define GH_SMEM (3*2*HTILE*2)

template<int MODE>
__global__ __launch_bounds__(256, 2)
void gemm_h(const __half* __restrict__ A, const __half* __restrict__ Bt,
            const float* __restrict__ bias, const float* __restrict__ res,
            void* __restrict__ Cv, int M, int N, int K) {
    extern __shared__ __half smh[];
    __half* As = smh;
    __half* Bs = smh + 3*HTILE;
    int bm = blockIdx.y * 128, bn = blockIdx.x * 128;
    int tid = threadIdx.x, warp = tid >> 5, lane = tid & 31;
    int grp = lane >> 2, tig = lane & 3;
    int wm = (warp >> 2) * 64, wn = (warp & 3) * 32;
    int sel = lane >> 3, lrow = lane & 7;
    int a_r = (sel & 1) * 8 + lrow, a_c = (sel >> 1) * 8;
    int b_r = (sel >> 1) * 8 + lrow, b_c = (sel & 1) * 8;
    uint32_t sAu = (uint32_t)__cvta_generic_to_shared(As);
    uint32_t sBu = (uint32_t)__cvta_generic_to_shared(Bs);
    int niter = K >> 6;

    float acc[4][4][4] = {};

    auto loadTile = [&](int it, int buf) {
        int k0 = it * 64;
        #pragma unroll
        for (int i = 0; i < 4; i++) {
            int c = tid + i * 256;
            int row = c >> 3, kq = c & 7;
            cpa16(sAu + (uint32_t)(buf*HTILE + row*ASH + kq*8) * 2,
                  A + (size_t)(bm + row) * K + k0 + kq * 8);
            cpa16(sBu + (uint32_t)(buf*HTILE + row*ASH + kq*8) * 2,
                  Bt + (size_t)(bn + row) * K + k0 + kq * 8);
        }
        CP_COMMIT();
    };

    loadTile(0, 0);
    loadTile(1, 1);

    for (int it = 0; it < niter; ++it) {
        CP_WAIT1();
        __syncthreads();
        if (it + 2 < niter) loadTile(it + 2, (it + 2) % 3);
        else CP_COMMIT();

        uint32_t Abu = sAu + (uint32_t)((it % 3) * HTILE) * 2;
        uint32_t Bbu = sBu + (uint32_t)((it % 3) * HTILE) * 2;
        #pragma unroll
        for (int ks = 0; ks < 64; ks += 16) {
            uint32_t af[4][4], bf[4][2];
            #pragma unroll
            for (int mf = 0; mf < 4; mf++) {
                uint32_t ad = Abu + (uint32_t)((wm + mf*16 + a_r) * ASH + ks + a_c) * 2;
                ldsm4(af[mf][0], af[mf][1], af[mf][2], af[mf][3], ad);
            }
            #pragma unroll
            for (int np = 0; np < 2; np++) {
                uint32_t bd = Bbu + (uint32_t)((wn + np*16 + b_r) * ASH + ks + b_c) * 2;
                ldsm4(bf[2*np][0], bf[2*np][1], bf[2*np+1][0], bf[2*np+1][1], bd);
            }
            #pragma unroll
            for (int mf = 0; mf < 4; mf++)
                #pragma unroll
                for (int nf = 0; nf < 4; nf++)
                    mma_f16(acc[mf][nf], af[mf][0], af[mf][1], af[mf][2], af[mf][3],
                            bf[nf][0], bf[nf][1]);
        }
    }

    #pragma unroll
    for (int mf = 0; mf < 4; mf++) {
        #pragma unroll
        for (int nf = 0; nf < 4; nf++) {
            int r = bm + wm + mf*16 + grp;
            int c = bn + wn + nf*8 + tig*2;
            float2 v0 = make_float2(acc[mf][nf][0], acc[mf][nf][1]);
            float2 v1 = make_float2(acc[mf][nf][2], acc[mf][nf][3]);
            if (MODE == 2) {
                int j = c >> 1;
                float bv = bias[j], bg = bias[FFd + j];
                float val0 = v0.x + bv, gat0 = v0.y + bg;
                float val1 = v1.x + bv, gat1 = v1.y + bg;
                float o0 = val0 * (0.5f * gat0 * (1.f + erff(gat0 * 0.70710678118654752f)));
                float o1 = val1 * (0.5f * gat1 * (1.f + erff(gat1 * 0.70710678118654752f)));
                __half* C = (__half*)Cv;
                C[(size_t)r * FFd + j]     = __float2half(o0);
                C[(size_t)(r+8) * FFd + j] = __float2half(o1);
            } else {
                if (bias) {
                    float2 bb = *(const float2*)(bias + c);
                    v0.x += bb.x; v0.y += bb.y; v1.x += bb.x; v1.y += bb.y;
                }
                if (MODE == 0 && res) {
                    float2 r0 = *(const float2*)(res + (size_t)r * N + c);
                    float2 r1 = *(const float2*)(res + (size_t)(r+8) * N + c);
                    v0.x += r0.x; v0.y += r0.y; v1.x += r1.x; v1.y += r1.y;
                }
                if (MODE == 1) {
                    __half* C = (__half*)Cv;
                    *(__half2*)(C + (size_t)r * N + c)     = __floats2half2_rn(v0.x, v0.y);
                    *(__half2*)(C + (size_t)(r+8) * N + c) = __floats2half2_rn(v1.x, v1.y);
                } else {
                    float* C = (float*)Cv;
                    *(float2*)(C + (size_t)r * N + c)     = v0;
                    *(float2*)(C + (size_t)(r+8) * N + c) = v1;
                }
            }
        }
    }
}

// ================= fp16 flash attention (register-P + double-buffered KV) ===
#define QSH 72
#define FTILE (128*QSH)
#define FLH_SMEM (5*FTILE*2)     // Q + 2*K + 2*V

__global__ __launch_bounds__(256, 2)
void flash_h(const __half* __restrict__ qkv, __half* __restrict__ o) {
    extern __shared__ __half smf[];
    __half* Qs = smf;
    uint32_t Qsu = (uint32_t)__cvta_generic_to_shared(Qs);
    uint32_t Ku[2] = { Qsu + (uint32_t)FTILE*2,   Qsu + (uint32_t)(2*FTILE)*2 };
    uint32_t Vu[2] = { Qsu + (uint32_t)(3*FTILE)*2, Qsu + (uint32_t)(4*FTILE)*2 };

    const int ldq = 3*Dm;
    int qt = blockIdx.x, bh = blockIdx.y;
    int b = bh >> 4, h = bh & 15;
    int tid = threadIdx.x, warp = tid >> 5, lane = tid & 31;
    int grp = lane >> 2, tig = lane & 3;
    int sel = lane >> 3, lrow = lane & 7;
    int a_r = (sel & 1) * 8 + lrow, a_c = (sel >> 1) * 8;
    int b_r = (sel >> 1) * 8 + lrow, b_c = (sel & 1) * 8;

    const __half* qb = qkv + ((size_t)b*SEQ + qt*128) * ldq + h*DHd;
    const __half* kb = qkv + (size_t)b*SEQ*ldq + Dm + h*DHd;
    const __half* vb = qkv + (size_t)b*SEQ*ldq + 2*Dm + h*DHd;

    {
        int row = tid >> 1, part = tid & 1;
        const float4* s4 = (const float4*)(qb + (size_t)row * ldq + part*32);
        float4* d4 = (float4*)(Qs + row*QSH + part*32);
        #pragma unroll
        for (int i = 0; i < 4; i++) d4[i] = s4[i];
    }

    auto loadKV = [&](int kv0, int buf) {
        #pragma unroll
        for (int i = 0; i < 4; i++) {
            int c = tid + i * 256;
            int row = c >> 3, kq = c & 7;
            cpa16(Ku[buf] + (uint32_t)(row*QSH + kq*8) * 2,
                  kb + (size_t)(kv0 + row) * ldq + kq * 8);
            cpa16(Vu[buf] + (uint32_t)(row*QSH + kq*8) * 2,
                  vb + (size_t)(kv0 + row) * ldq + kq * 8);
        }
        CP_COMMIT();
    };
    loadKV(0, 0);

    __syncthreads();
    uint32_t qf[4][4];
    {
        const __half* p = Qs + (warp*16 + grp) * QSH;
        #pragma unroll
        for (int ksi = 0; ksi < 4; ksi++) {
            qf[ksi][0] = *(const uint32_t*)(p + ksi*16 + tig*2);
            qf[ksi][1] = *(const uint32_t*)(p + 8*QSH + ksi*16 + tig*2);
            qf[ksi][2] = *(const uint32_t*)(p + ksi*16 + tig*2 + 8);
            qf[ksi][3] = *(const uint32_t*)(p + 8*QSH + ksi*16 + tig*2 + 8);
        }
    }

    float oacc[8][4] = {};
    float m0 = -1e30f, m1 = -1e30f, l0 = 0.f, l1 = 0.f;
    const float Csc = SCALE_ATTN * 1.4426950408889634f;

    for (int it = 0; it < SEQ/128; ++it) {
        int buf = it & 1;
        CP_WAIT0();
        __syncthreads();
        if (it + 1 < SEQ/128) loadKV((it + 1) * 128, buf ^ 1);

        float sacc[16][4] = {};
        #pragma unroll
        for (int ksi = 0; ksi < 4; ksi++) {
            #pragma unroll
            for (int np = 0; np < 8; np++) {
                uint32_t kd = Ku[buf] + (uint32_t)((np*16 + b_r) * QSH + ksi*16 + b_c) * 2;
                uint32_t b00, b01, b10, b11;
                ldsm4(b00, b01, b10, b11, kd);
                mma_f16(sacc[2*np],   qf[ksi][0], qf[ksi][1], qf[ksi][2], qf[ksi][3], b00, b01);
                mma_f16(sacc[2*np+1], qf[ksi][0], qf[ksi][1], qf[ksi][2], qf[ksi][3], b10, b11);
            }
        }
        float mx0 = -1e30f, mx1 = -1e30f;
        #pragma unroll
        for (int nf = 0; nf < 16; nf++) {
            sacc[nf][0] *= Csc; sacc[nf][1] *= Csc; sacc[nf][2] *= Csc; sacc[nf][3] *= Csc;
            mx0 = fmaxf(mx0, fmaxf(sacc[nf][0], sacc[nf][1]));
            mx1 = fmaxf(mx1, fmaxf(sacc[nf][2], sacc[nf][3]));
        }
        mx0 = fmaxf(mx0, __shfl_xor_sync(0xffffffffu, mx0, 1));
        mx0 = fmaxf(mx0, __shfl_xor_sync(0xffffffffu, mx0, 2));
        mx1 = fmaxf(mx1, __shfl_xor_sync(0xffffffffu, mx1, 1));
        mx1 = fmaxf(mx1, __shfl_xor_sync(0xffffffffu, mx1, 2));
        float mn0 = fmaxf(m0, mx0), mn1 = fmaxf(m1, mx1);
        float sc0 = ex2f(m0 - mn0), sc1 = ex2f(m1 - mn1);
        float sum0 = 0.f, sum1 = 0.f;
        uint32_t ph[16][2];
        #pragma unroll
        for (int nf = 0; nf < 16; nf++) {
            float p0 = ex2f(sacc[nf][0] - mn0);
            float p1 = ex2f(sacc[nf][1] - mn0);
            float p2 = ex2f(sacc[nf][2] - mn1);
            float p3 = ex2f(sacc[nf][3] - mn1);
            sum0 += p0 + p1; sum1 += p2 + p3;
            ph[nf][0] = pack_h2(p0, p1);
            ph[nf][1] = pack_h2(p2, p3);
        }
        sum0 += __shfl_xor_sync(0xffffffffu, sum0, 1);
        sum0 += __shfl_xor_sync(0xffffffffu, sum0, 2);
        sum1 += __shfl_xor_sync(0xffffffffu, sum1, 1);
        sum1 += __shfl_xor_sync(0xffffffffu, sum1, 2);
        l0 = l0 * sc0 + sum0;  l1 = l1 * sc1 + sum1;
        m0 = mn0;  m1 = mn1;
        #pragma unroll
        for (int nf = 0; nf < 8; nf++) {
            oacc[nf][0] *= sc0; oacc[nf][1] *= sc0;
            oacc[nf][2] *= sc1; oacc[nf][3] *= sc1;
        }

        #pragma unroll
        for (int ks = 0; ks < 8; ks++) {
            uint32_t a0 = ph[2*ks][0], a1 = ph[2*ks][1];
            uint32_t a2 = ph[2*ks+1][0], a3 = ph[2*ks+1][1];
            #pragma unroll
            for (int np = 0; np < 4; np++) {
                uint32_t vd = Vu[buf] + (uint32_t)((ks*16 + a_r) * QSH + np*16 + a_c) * 2;
                uint32_t b00, b01, b10, b11;
                ldsm4t(b00, b01, b10, b11, vd);
                mma_f16(oacc[2*np],   a0, a1, a2, a3, b00, b01);
                mma_f16(oacc[2*np+1], a0, a1, a2, a3, b10, b11);
            }
        }
    }

    float i0 = 1.f / l0, i1 = 1.f / l1;
    __half* ob = o + ((size_t)b*SEQ + qt*128 + warp*16) * Dm + h*DHd;
    #pragma unroll
    for (int nf = 0; nf < 8; nf++) {
        int c = nf*8 + tig*2;
        *(__half2*)(ob + (size_t)grp * Dm + c) =
            __floats2half2_rn(oacc[nf][0]*i0, oacc[nf][1]*i0);
        *(__half2*)(ob + (size_t)(grp+8) * Dm + c) =
            __floats2half2_rn(oacc[nf][2]*i1, oacc[nf][3]*i1);
    }
}

// ================= fp16 cross-attention (single fused KV tile, nk=77) =======
#define CKROWS 80
#define LDKV (2*Dm)
#define FLC_SMEM ((128*QSH + 2*CKROWS*QSH)*2)

__global__ __launch_bounds__(256, 2)
void flash_cross(const __half* __restrict__ q, const __half* __restrict__ kv,
                 __half* __restrict__ o) {
    extern __shared__ __half smc[];
    __half* Qs = smc;
    __half* Ks = Qs + 128*QSH;
    __half* Vs = Ks + CKROWS*QSH;
    uint32_t Vsu = (uint32_t)__cvta_generic_to_shared(Vs);

    int qt = blockIdx.x, bh = blockIdx.y;
    int b = bh >> 4, h = bh & 15;
    int tid = threadIdx.x, warp = tid >> 5, lane = tid & 31;
    int grp = lane >> 2, tig = lane & 3;
    int sel = lane >> 3, lrow = lane & 7;
    int a_r = (sel & 1) * 8 + lrow, a_c = (sel >> 1) * 8;

    const __half* qb = q + ((size_t)b*SEQ + qt*128) * Dm + h*DHd;
    const __half* kb = kv + (size_t)b*NCx*LDKV + h*DHd;
    const __half* vb = kb + Dm;

    {
        int row = tid >> 1, part = tid & 1;
        const float4* s4 = (const float4*)(qb + (size_t)row * Dm + part*32);
        float4* d4 = (float4*)(Qs + row*QSH + part*32);
        #pragma unroll
        for (int i = 0; i < 4; i++) d4[i] = s4[i];
    }
    for (int rr = tid; rr < CKROWS*2; rr += 256) {
        int row = rr >> 1, part = rr & 1;
        float4* dk = (float4*)(Ks + row*QSH + part*32);
        float4* dv = (float4*)(Vs + row*QSH + part*32);
        if (row < NCx) {
            const float4* sk = (const float4*)(kb + (size_t)row * LDKV + part*32);
            const float4* sv = (const float4*)(vb + (size_t)row * LDKV + part*32);
            #pragma unroll
            for (int i = 0; i < 4; i++) { dk[i] = sk[i]; dv[i] = sv[i]; }
        } else {
            float4 z = make_float4(0.f,0.f,0.f,0.f);
            #pragma unroll
            for (int i = 0; i < 4; i++) { dk[i] = z; dv[i] = z; }
        }
    }
    __syncthreads();

    uint32_t qf[4][4];
    {
        const __half* p = Qs + (warp*16 + grp) * QSH;
        #pragma unroll
        for (int ksi = 0; ksi < 4; ksi++) {
            qf[ksi][0] = *(const uint32_t*)(p + ksi*16 + tig*2);
            qf[ksi][1] = *(const uint32_t*)(p + 8*QSH + ksi*16 + tig*2);
            qf[ksi][2] = *(const uint32_t*)(p + ksi*16 + tig*2 + 8);
            qf[ksi][3] = *(const uint32_t*)(p + 8*QSH + ksi*16 + tig*2 + 8);
        }
    }

    const float Csc = SCALE_ATTN * 1.4426950408889634f;

    float sacc[10][4] = {};
    #pragma unroll
    for (int ksi = 0; ksi < 4; ksi++) {
        #pragma unroll
        for (int nf = 0; nf < 10; nf++) {
            const __half* kp = Ks + (nf*8 + grp) * QSH + ksi*16;
            uint32_t b0 = *(const uint32_t*)(kp + tig*2);
            uint32_t b1 = *(const uint32_t*)(kp + tig*2 + 8);
            mma_f16(sacc[nf], qf[ksi][0], qf[ksi][1], qf[ksi][2], qf[ksi][3], b0, b1);
        }
    }
    float mx0 = -1e30f, mx1 = -1e30f;
    #pragma unroll
    for (int nf = 0; nf < 10; nf++) {
        int c0 = nf*8 + tig*2, c1 = c0 + 1;
        sacc[nf][0] = (c0 < NCx) ? sacc[nf][0]*Csc : -1e30f;
        sacc[nf][1] = (c1 < NCx) ? sacc[nf][1]*Csc : -1e30f;
        sacc[nf][2] = (c0 < NCx) ? sacc[nf][2]*Csc : -1e30f;
        sacc[nf][3] = (c1 < NCx) ? sacc[nf][3]*Csc : -1e30f;
        mx0 = fmaxf(mx0, fmaxf(sacc[nf][0], sacc[nf][1]));
        mx1 = fmaxf(mx1, fmaxf(sacc[nf][2], sacc[nf][3]));
    }
    mx0 = fmaxf(mx0, __shfl_xor_sync(0xffffffffu, mx0, 1));
    mx0 = fmaxf(mx0, __shfl_xor_sync(0xffffffffu, mx0, 2));
    mx1 = fmaxf(mx1, __shfl_xor_sync(0xffffffffu, mx1, 1));
    mx1 = fmaxf(mx1, __shfl_xor_sync(0xffffffffu, mx1, 2));

    float sum0 = 0.f, sum1 = 0.f;
    uint32_t ph[10][2];
    #pragma unroll
    for (int nf = 0; nf < 10; nf++) {
        float p0 = ex2f(sacc[nf][0] - mx0);
        float p1 = ex2f(sacc[nf][1] - mx0);
        float p2 = ex2f(sacc[nf][2] - mx1);
        float p3 = ex2f(sacc[nf][3] - mx1);
        sum0 += p0 + p1; sum1 += p2 + p3;
        ph[nf][0] = pack_h2(p0, p1);
        ph[nf][1] = pack_h2(p2, p3);
    }
    sum0 += __shfl_xor_sync(0xffffffffu, sum0, 1);
    sum0 += __shfl_xor_sync(0xffffffffu, sum0, 2);
    sum1 += __shfl_xor_sync(0xffffffffu, sum1, 1);
    sum1 += __shfl_xor_sync(0xffffffffu, sum1, 2);

    float oacc[8][4] = {};
    #pragma unroll
    for (int ks = 0; ks < 5; ks++) {
        uint32_t a0 = ph[2*ks][0], a1 = ph[2*ks][1];
        uint32_t a2 = ph[2*ks+1][0], a3 = ph[2*ks+1][1];
        #pragma unroll
        for (int np = 0; np < 4; np++) {
            uint32_t vd = Vsu + (uint32_t)((ks*16 + a_r) * QSH + np*16 + a_c) * 2;
            uint32_t b00, b01, b10, b11;
            ldsm4t(b00, b01, b10, b11, vd);
            mma_f16(oacc[2*np],   a0, a1, a2, a3, b00, b01);
            mma_f16(oacc[2*np+1], a0, a1, a2, a3, b10, b11);
        }
    }

    float i0 = 1.f / sum0, i1 = 1.f / sum1;
    __half* ob = o + ((size_t)b*SEQ + qt*128 + warp*16) * Dm + h*DHd;
    #pragma unroll
    for (int nf = 0; nf < 8; nf++) {
        int c = nf*8 + tig*2;
        *(__half2*)(ob + (size_t)grp * Dm + c) =
            __floats2half2_rn(oacc[nf][0]*i0, oacc[nf][1]*i0);
        *(__half2*)(ob + (size_t)(grp+8) * Dm + c) =
            __floats2half2_rn(oacc[nf][2]*i1, oacc[nf][3]*i1);
    }
}

// ---------------- layernorm: single-pass float4 + warp shuffle ----------------
__global__ __launch_bounds__(256)
void ln_kernel(const float* __restrict__ x, const float* __restrict__ g,
               const float* __restrict__ b, __half* __restrict__ out) {
    int row = blockIdx.x;
    int tid = threadIdx.x, warp = tid >> 5, lane = tid & 31;
    const float4* xr = (const float4*)(x + (size_t)row * Dm);
    float4 v = xr[tid];
    float s  = v.x + v.y + v.z + v.w;
    float ss = v.x*v.x + v.y*v.y + v.z*v.z + v.w*v.w;
    #pragma unroll
    for (int o = 16; o > 0; o >>= 1) {
        s  += __shfl_xor_sync(0xffffffffu, s,  o);
        ss += __shfl_xor_sync(0xffffffffu, ss, o);
    }
    __shared__ float ws[8], wss[8];
    if (lane == 0) { ws[warp] = s; wss[warp] = ss; }
    __syncthreads();
    float ts = 0.f, tss = 0.f;
    #pragma unroll
    for (int i = 0; i < 8; i++) { ts += ws[i]; tss += wss[i]; }
    float mu  = ts * (1.0f / Dm);
    float var = tss * (1.0f / Dm) - mu * mu;
    float inv = rsqrtf(var + EPS_LN);
    float4 gv = ((const float4*)g)[tid];
    float4 bv = ((const float4*)b)[tid];
    float o0 = (v.x - mu) * inv * gv.x + bv.x;
    float o1 = (v.y - mu) * inv * gv.y + bv.y;
    float o2 = (v.z - mu) * inv * gv.z + bv.z;
    float o3 = (v.w - mu) * inv * gv.w + bv.w;
    __half2* orow = (__half2*)(out + (size_t)row * Dm) + tid * 2;
    orow[0] = __floats2half2_rn(o0, o1);
    orow[1] = __floats2half2_rn(o2, o3);
}

// ---------------- launch ----------------
extern "C" void kernel_launch(void* const* d_in, const int* in_sizes, int n_in,
                              void* d_out, int out_size) {
    const float* x      = (const float*)d_in[0];
    const float* ctx    = (const float*)d_in[1];
    const float* w1_q   = (const float*)d_in[2];
    const float* w1_k   = (const float*)d_in[3];
    const float* w1_v   = (const float*)d_in[4];
    const float* w1_o   = (const float*)d_in[5];
    const float* b1_o   = (const float*)d_in[6];
    const float* w2_q   = (const float*)d_in[7];
    const float* w2_k   = (const float*)d_in[8];
    const float* w2_v   = (const float*)d_in[9];
    const float* w2_o   = (const float*)d_in[10];
    const float* b2_o   = (const float*)d_in[11];
    const float* ln1_g  = (const float*)d_in[12];
    const float* ln1_b  = (const float*)d_in[13];
    const float* ln2_g  = (const float*)d_in[14];
    const float* ln2_b  = (const float*)d_in[15];
    const float* ln3_g  = (const float*)d_in[16];
    const float* ln3_b  = (const float*)d_in[17];
    const float* ff_w1  = (const float*)d_in[18];
    const float* ff_b1  = (const float*)d_in[19];
    const float* ff_w2  = (const float*)d_in[20];
    const float* ff_b2  = (const float*)d_in[21];
    float* xbuf = (float*)d_out;

    __half *hh, *qkvh, *ctxh, *kvh, *atth, *th, *wh;
    cudaGetSymbolAddress((void**)&hh,   g_hh);
    cudaGetSymbolAddress((void**)&qkvh, g_qkv);
    cudaGetSymbolAddress((void**)&ctxh, g_ctxh);
    cudaGetSymbolAddress((void**)&kvh,  g_kvh);
    cudaGetSymbolAddress((void**)&atth, g_atth);
    cudaGetSymbolAddress((void**)&th,   g_th);
    cudaGetSymbolAddress((void**)&wh,   g_wh);

    cudaFuncSetAttribute(gemm_h<0>, cudaFuncAttributeMaxDynamicSharedMemorySize, GH_SMEM);
    cudaFuncSetAttribute(gemm_h<1>, cudaFuncAttributeMaxDynamicSharedMemorySize, GH_SMEM);
    cudaFuncSetAttribute(gemm_h<2>, cudaFuncAttributeMaxDynamicSharedMemorySize, GH_SMEM);
    cudaFuncSetAttribute(flash_h,     cudaFuncAttributeMaxDynamicSharedMemorySize, FLH_SMEM);
    cudaFuncSetAttribute(flash_cross, cudaFuncAttributeMaxDynamicSharedMemorySize, FLC_SMEM);

    dim3 gD(Dm/128, MROWS/128);
    dim3 gQKV(3*Dm/128, MROWS/128);
    dim3 gFF1(2*FFd/128, MROWS/128);
    dim3 gFlash(SEQ/128, Bq*Hh);
    dim3 gKVt(2*Dm/128, CPAD/128);           // (16, 2) for fused KV projection
    dim3 tpb(32, 8);

    transpose_half6<<<dim3(Dm/32, Dm/32, 6), tpb>>>(
        w1_q, w1_k, w1_v, w1_o, w2_q, w2_o,
        wh+OWQKV, wh+OWQKV+1024*1024, wh+OWQKV+2*1024*1024,
        wh+OW1O, wh+OW2Q, wh+OW2O);
    transpose_geglu<<<dim3(2*FFd/32, Dm/32), tpb>>>(ff_w1, wh+OFW1, Dm,  2*FFd);
    transpose_half<<<dim3(Dm/32,  FFd/32),  tpb>>>(ff_w2, wh+OFW2, FFd, Dm);
    transpose_half<<<dim3(Dm/32,  DCx/32),  tpb>>>(w2_k, wh+OKV,            DCx, Dm);
    transpose_half<<<dim3(Dm/32,  DCx/32),  tpb>>>(w2_v, wh+OKV+Dm*DCx,     DCx, Dm);
    ctx_to_half<<<(CPAD*DCx/2 + 255)/256, 256>>>(ctx, ctxh);

    // ---- self attention ----
    ln_kernel<<<MROWS, 256>>>(x, ln1_g, ln1_b, hh);
    gemm_h<1><<<gQKV, 256, GH_SMEM>>>(hh, wh+OWQKV, nullptr, nullptr, qkvh, MROWS, 3*Dm, Dm);
    flash_h<<<gFlash, 256, FLH_SMEM>>>(qkvh, atth);
    gemm_h<0><<<gD, 256, GH_SMEM>>>(atth, wh+OW1O, b1_o, x, xbuf, MROWS, Dm, Dm);

    // ---- cross attention ----
    ln_kernel<<<MROWS, 256>>>(xbuf, ln2_g, ln2_b, hh);
    gemm_h<1><<<gD, 256, GH_SMEM>>>(hh, wh+OW2Q, nullptr, nullptr, atth, MROWS, Dm, Dm);
    gemm_h<1><<<gKVt, 256, GH_SMEM>>>(ctxh, wh+OKV, nullptr, nullptr, kvh, CPAD, 2*Dm, DCx);
    flash_cross<<<gFlash, 256, FLC_SMEM>>>(atth, kvh, qkvh);
    gemm_h<0><<<gD, 256, GH_SMEM>>>(qkvh, wh+OW2O, b2_o, xbuf, xbuf, MROWS, Dm, Dm);

    // ---- GEGLU FFN ----
    ln_kernel<<<MROWS, 256>>>(xbuf, ln3_g, ln3_b, hh);
    gemm_h<2><<<gFF1, 256, GH_SMEM>>>(hh, wh+OFW1, ff_b1, nullptr, th, MROWS, 2*FFd, Dm);
    gemm_h<0><<<gD, 256, GH_SMEM>>>(th, wh+OFW2, ff_b2, xbuf, xbuf, MROWS, Dm, FFd);
}